// round 8
// baseline (speedup 1.0000x reference)
#include <cuda_runtime.h>
#include <math.h>

// Problem constants
#define F_DIM   512
#define B_DIM   512
#define L_DIM   256
#define C_DIM   128

#define GRID_BLOCKS 128
#define THREADS     512
#define FT   16      // f rows per block
#define BT   128     // batch cols per block
#define KCH  64      // k-chunk rows in smem
#define WST  64      // Wsh row stride in floats

// Persistent device state (allowed: __device__ globals, no allocation)
__device__ float g_h[2][F_DIM * B_DIM];
__device__ unsigned g_bar_count;
__device__ volatile unsigned g_bar_sense;

typedef unsigned long long u64;

__device__ __forceinline__ u64 pack2(float w) {
    u64 r; asm("mov.b64 %0, {%1, %1};" : "=l"(r) : "f"(w)); return r;
}
__device__ __forceinline__ void fma2(u64 &d, u64 a, u64 b) {
    asm("fma.rn.f32x2 %0, %1, %2, %0;" : "+l"(d) : "l"(a), "l"(b));
}
__device__ __forceinline__ float2 unpack2(u64 v) {
    float2 f; asm("mov.b64 {%0, %1}, %2;" : "=f"(f.x), "=f"(f.y) : "l"(v)); return f;
}

// Accurate activations that do NOT degrade under fast-math builds.
__device__ __forceinline__ float sigm(float x) {
    const float e = exp2f(-1.4426950408889634f * x);
    return 1.0f / (1.0f + e);
}
__device__ __forceinline__ float tanh_acc(float x) {
    const float xc = fminf(fmaxf(x, -9.0f), 9.0f);   // tanh(|x|>9) == 1.0f in fp32
    const float e = exp2f(2.8853900817779268f * xc); // exp(2x)
    return (e - 1.0f) / (e + 1.0f);
}

// Grid-wide sense-reversing barrier; initial sense read from global at kernel
// start so the odd per-launch barrier count stays replay-deterministic.
__device__ __forceinline__ void gsync(unsigned* s_sense) {
    __threadfence();          // release this thread's prior global stores
    __syncthreads();
    if (threadIdx.x == 0) {
        unsigned ns = *s_sense ^ 1u;
        *s_sense = ns;
        unsigned old = atomicAdd(&g_bar_count, 1u);
        if (old == GRID_BLOCKS - 1u) {
            g_bar_count = 0u;
            __threadfence();
            g_bar_sense = ns;
        } else {
            while (g_bar_sense != ns) { }
        }
    }
    __syncthreads();
    __threadfence();          // acquire + L1 invalidate
    __syncthreads();
}

__global__ void __launch_bounds__(THREADS, 1)
lstm_persist_kernel(const float* __restrict__ x,
                    const float* __restrict__ w_gx, const float* __restrict__ w_gh,
                    const float* __restrict__ w_ix, const float* __restrict__ w_ih,
                    const float* __restrict__ w_fx, const float* __restrict__ w_fh,
                    const float* __restrict__ w_ox, const float* __restrict__ w_oh,
                    const float* __restrict__ w_ph,
                    const float* __restrict__ b_g, const float* __restrict__ b_i,
                    const float* __restrict__ b_f, const float* __restrict__ b_o,
                    const float* __restrict__ b_p,
                    float* __restrict__ out)
{
    extern __shared__ float smem[];
    float* Wsh = smem;                  // [512][WST] transposed weights: Wsh[k][fl*4+gate]
    float* hs0 = Wsh + F_DIM * WST;     // [KCH][BT] h chunk, buffer 0
    float* hs1 = hs0 + KCH * BT;        // [KCH][BT] h chunk, buffer 1
    float* sx  = hs1 + KCH * BT;        // [BT] x slice for this step
    float* swx = sx + BT;               // [64] per-row w_*x value

    const int tid   = threadIdx.x;
    const int bid   = blockIdx.x;
    const int ftile = bid & 31;         // 32 f-tiles of 16 rows
    const int btile = bid >> 5;         // 4 b-tiles of 128 cols
    const int rg    = tid >> 6;         // 0..7 : owns gate-rows rg*8 .. rg*8+7
    const int cg    = tid & 63;         // 0..63: owns cols cg*2, cg*2+1
    const int b0    = btile * BT;
    const int cbase = cg << 1;

    __shared__ unsigned s_sense;
    if (tid == 0) s_sense = g_bar_sense;   // safe: sense can't change until this block arrives

    // ---- Load stationary weights, transposed: row r = fl*4 + gate ----
    {
        const float* Wh[4] = {w_gh, w_ih, w_fh, w_oh};
        #pragma unroll 1
        for (int r = 0; r < 64; ++r) {
            const int fl = r >> 2, gt = r & 3;
            Wsh[tid * WST + r] = Wh[gt][(ftile * FT + fl) * F_DIM + tid];
        }
        if (tid < 64) {
            const int fl = tid >> 2, gt = tid & 3, f = ftile * FT + fl;
            const float* Wx[4] = {w_gx, w_ix, w_fx, w_ox};
            swx[tid] = Wx[gt][f];
        }
    }

    // Reference semantics: gate biases (F,)==(B,) broadcast along the TRAILING
    // (batch) axis -> bias indexed by BATCH column, not feature row.
    float bgc[2], bic[2], bfc[2], boc[2];
    #pragma unroll
    for (int ci = 0; ci < 2; ++ci) {
        const int b = b0 + cbase + ci;
        bgc[ci] = b_g[b];
        bic[ci] = b_i[b];
        bfc[ci] = b_f[b];
        boc[ci] = b_o[b];
    }

    // ---- Zero our tile of h buffer 0 (h0 = 0) ----
    for (int q = tid; q < FT * BT; q += THREADS) {
        const int fl = q >> 7, c = q & 127;
        g_h[0][(ftile * FT + fl) * B_DIM + b0 + c] = 0.0f;
    }
    gsync(&s_sense);

    // ---- Recurrence state ----
    // acc[p][c]: f32x2 over ROWS: lanes = gate-rows (rg*8+2p, rg*8+2p+1),
    // batch col = cbase+c.  p=0: (g,i) fl0; p=1: (f,o) fl0; p=2,3: fl1.
    u64   acc[4][2];
    float cst[4];         // c state: 2 f-rows x 2 cols, cst[fl2*2+c]
    #pragma unroll
    for (int p = 0; p < 4; ++p) { acc[p][0] = 0ull; acc[p][1] = 0ull; }
    #pragma unroll
    for (int i = 0; i < 4; ++i) cst[i] = 0.0f;

    for (int t = 0; t < L_DIM; ++t) {
        const float* __restrict__ hsrc = g_h[t & 1];
        float* __restrict__ hdst = g_h[(t & 1) ^ 1];

        // prefetch chunk 0 into registers (4 float4 per thread)
        float4 pf[4];
        #pragma unroll
        for (int q = 0; q < 4; ++q) {
            const int idx = tid + (q << 9);
            const int kk = idx >> 5, c4 = idx & 31;
            pf[q] = *(const float4*)&hsrc[kk * B_DIM + b0 + (c4 << 2)];
        }
        if (tid < BT) sx[tid] = x[(b0 + tid) * L_DIM + t];

        for (int kc = 0; kc < 8; ++kc) {
            float* buf = (kc & 1) ? hs1 : hs0;
            // Stage chunk kc. Safe vs. other threads still computing chunk
            // kc-1: they read the OTHER buffer. Single sync per chunk.
            #pragma unroll
            for (int q = 0; q < 4; ++q)
                ((float4*)buf)[tid + (q << 9)] = pf[q];
            if (kc < 7) {                           // prefetch next chunk (overlaps compute)
                #pragma unroll
                for (int q = 0; q < 4; ++q) {
                    const int idx = tid + (q << 9);
                    const int kk = idx >> 5, c4 = idx & 31;
                    pf[q] = *(const float4*)&hsrc[((kc + 1) * KCH + kk) * B_DIM + b0 + (c4 << 2)];
                }
            }
            __syncthreads();

            const float* wbase = Wsh + (kc * KCH) * WST + (rg << 3);
            const float* hbase = buf + cbase;
            #pragma unroll 4
            for (int kk = 0; kk < KCH; ++kk) {
                // weights: 8 consecutive rows -> 4 ready-made f32x2 pairs
                // (two broadcast LDS.128, zero packing MOVs)
                const u64* wp = (const u64*)(wbase + (kk << 6));
                const u64 w0 = wp[0], w1 = wp[1], w2 = wp[2], w3 = wp[3];
                // h: 2 scalars from one LDS.64, packed with 2 MOVs
                const float2 hv2 = *(const float2*)(hbase + (kk << 7));
                const u64 h0 = pack2(hv2.x), h1 = pack2(hv2.y);
                fma2(acc[0][0], w0, h0); fma2(acc[0][1], w0, h1);
                fma2(acc[1][0], w1, h0); fma2(acc[1][1], w1, h1);
                fma2(acc[2][0], w2, h0); fma2(acc[2][1], w2, h1);
                fma2(acc[3][0], w3, h0); fma2(acc[3][1], w3, h1);
            }
        }

        // ---- Gates + state update for owned (2 f-rows x 2 cols) ----
        const float xv[2] = {sx[cbase + 0], sx[cbase + 1]};
        #pragma unroll
        for (int fl2 = 0; fl2 < 2; ++fl2) {
            const int r0 = (rg << 3) + (fl2 << 2);
            const int fl = (rg << 1) + fl2;
            float2 hv;
            float* hvp = (float*)&hv;
            #pragma unroll
            for (int ci = 0; ci < 2; ++ci) {
                const float2 gi = unpack2(acc[(fl2 << 1) + 0][ci]);  // (g, i)
                const float2 fo = unpack2(acc[(fl2 << 1) + 1][ci]);  // (f, o)
                const float pg  = gi.x + swx[r0 + 0] * xv[ci] + bgc[ci];
                const float pi  = gi.y + swx[r0 + 1] * xv[ci] + bic[ci];
                const float pff = fo.x + swx[r0 + 2] * xv[ci] + bfc[ci];
                const float po  = fo.y + swx[r0 + 3] * xv[ci] + boc[ci];
                const float gg = tanh_acc(pg);
                const float si = sigm(pi);
                const float sf = sigm(pff);
                const float so = sigm(po);
                const float cn = gg * si + cst[(fl2 << 1) + ci] * sf;
                cst[(fl2 << 1) + ci] = cn;
                hvp[ci] = tanh_acc(cn) * so;
            }
            *(float2*)&hdst[(ftile * FT + fl) * B_DIM + b0 + cbase] = hv;
        }
        #pragma unroll
        for (int p = 0; p < 4; ++p) { acc[p][0] = 0ull; acc[p][1] = 0ull; }
        gsync(&s_sense);
    }

    // ---- Projection: p = h^T @ w_ph + b_p ; final h is in g_h[0] (L even) ----
    {
        const float* __restrict__ hfin = g_h[0];
        const int c = tid & 127;
        const int brow = (bid << 2) + (tid >> 7);   // block owns 4 batch rows
        float a0 = 0.0f;
        #pragma unroll 4
        for (int f = 0; f < F_DIM; ++f) {
            a0 += hfin[f * B_DIM + brow] * w_ph[f * C_DIM + c];
        }
        out[brow * C_DIM + c] = a0 + b_p[c];
    }
}

extern "C" void kernel_launch(void* const* d_in, const int* in_sizes, int n_in,
                              void* d_out, int out_size)
{
    (void)in_sizes; (void)n_in; (void)out_size;
    const float* x    = (const float*)d_in[0];
    const float* w_gx = (const float*)d_in[1];
    const float* w_gh = (const float*)d_in[2];
    const float* w_ix = (const float*)d_in[3];
    const float* w_ih = (const float*)d_in[4];
    const float* w_fx = (const float*)d_in[5];
    const float* w_fh = (const float*)d_in[6];
    const float* w_ox = (const float*)d_in[7];
    const float* w_oh = (const float*)d_in[8];
    const float* w_ph = (const float*)d_in[9];
    const float* b_g  = (const float*)d_in[10];
    const float* b_i  = (const float*)d_in[11];
    const float* b_f  = (const float*)d_in[12];
    const float* b_o  = (const float*)d_in[13];
    const float* b_p  = (const float*)d_in[14];
    float* out = (float*)d_out;

    const size_t smem_bytes = (size_t)(F_DIM * WST + 2 * KCH * BT + BT + 64) * sizeof(float);
    cudaFuncSetAttribute(lstm_persist_kernel,
                         cudaFuncAttributeMaxDynamicSharedMemorySize, (int)smem_bytes);

    lstm_persist_kernel<<<GRID_BLOCKS, THREADS, smem_bytes>>>(
        x, w_gx, w_gh, w_ix, w_ih, w_fx, w_fh, w_ox, w_oh, w_ph,
        b_g, b_i, b_f, b_o, b_p, out);
}

// round 10
// speedup vs baseline: 1.6486x; 1.6486x over previous
#include <cuda_runtime.h>
#include <cuda_bf16.h>
#include <math.h>

typedef unsigned int u32;

#define F_DIM 512
#define B_DIM 512
#define L_DIM 256
#define C_DIM 128

#define GRID_BLOCKS 128
#define THREADS 256
#define FT    16      // features per CTA
#define NGATE 64      // gate cols per CTA (MMA N)
#define BT    128     // batch rows per CTA (MMA M)
#define KC    64      // k-chunk
#define NCH   8       // chunks per step

#define BST 520       // B row stride in bf16 (pad: conflict-free ldmatrix)
#define AST 72        // A row stride in bf16

// SMEM byte offsets
#define B_PLANE_BYTES (NGATE * BST * 2)          // 66560
#define BHI_OFF 0
#define BLO_OFF B_PLANE_BYTES
#define A_PLANE_BYTES (BT * AST * 2)             // 18432
#define A_OFF   (2 * B_PLANE_BYTES)              // 133120
#define AHI_OFF(p) (A_OFF + (p) * 2 * A_PLANE_BYTES)
#define ALO_OFF(p) (AHI_OFF(p) + A_PLANE_BYTES)
#define SX_OFF   (A_OFF + 4 * A_PLANE_BYTES)     // 206848 (128 floats)
#define SWX_OFF  (SX_OFF + 512)                  // 64 floats
#define SB_OFF   (SWX_OFF + 256)                 // 4 x 128 floats
#define SMEM_TOTAL (SB_OFF + 2048 + 64)          // ~209.8 KB

// Persistent device state
__device__ __nv_bfloat16 g_hh[2][B_DIM * F_DIM];   // h^T hi plane [batch][feat]
__device__ __nv_bfloat16 g_hl[2][B_DIM * F_DIM];   // h^T lo plane
__device__ unsigned g_bar_count;
__device__ volatile unsigned g_bar_sense;

__device__ __forceinline__ u32 smem_u32(const void* p) {
    u32 a; asm("{ .reg .u64 t; cvta.to.shared.u64 t, %1; cvt.u32.u64 %0, t; }" : "=r"(a) : "l"(p));
    return a;
}
__device__ __forceinline__ void ldsm_x4(u32& r0, u32& r1, u32& r2, u32& r3, u32 addr) {
    asm volatile("ldmatrix.sync.aligned.m8n8.x4.shared.b16 {%0,%1,%2,%3}, [%4];"
                 : "=r"(r0), "=r"(r1), "=r"(r2), "=r"(r3) : "r"(addr));
}
__device__ __forceinline__ void mma16816(float* c, const u32* a, u32 b0, u32 b1) {
    asm volatile("mma.sync.aligned.m16n8k16.row.col.f32.bf16.bf16.f32 "
                 "{%0,%1,%2,%3}, {%4,%5,%6,%7}, {%8,%9}, {%0,%1,%2,%3};"
                 : "+f"(c[0]), "+f"(c[1]), "+f"(c[2]), "+f"(c[3])
                 : "r"(a[0]), "r"(a[1]), "r"(a[2]), "r"(a[3]), "r"(b0), "r"(b1));
}

// Accurate activations (fast-math-safe: ex2.approx ~2^-22)
__device__ __forceinline__ float sigm(float x) {
    const float e = exp2f(-1.4426950408889634f * x);
    return 1.0f / (1.0f + e);
}
__device__ __forceinline__ float tanh_acc(float x) {
    const float xc = fminf(fmaxf(x, -9.0f), 9.0f);
    const float e = exp2f(2.8853900817779268f * xc);
    return (e - 1.0f) / (e + 1.0f);
}

// Grid-wide sense-reversing barrier (replay-safe: initial sense read at start)
__device__ __forceinline__ void gsync(unsigned* s_sense) {
    __threadfence();
    __syncthreads();
    if (threadIdx.x == 0) {
        unsigned ns = *s_sense ^ 1u;
        *s_sense = ns;
        unsigned old = atomicAdd(&g_bar_count, 1u);
        if (old == GRID_BLOCKS - 1u) {
            g_bar_count = 0u;
            __threadfence();
            g_bar_sense = ns;
        } else {
            while (g_bar_sense != ns) { }
        }
    }
    __syncthreads();
    __threadfence();
    __syncthreads();
}

__global__ void __launch_bounds__(THREADS, 1)
lstm_hmma_kernel(const float* __restrict__ x,
                 const float* __restrict__ w_gx, const float* __restrict__ w_gh,
                 const float* __restrict__ w_ix, const float* __restrict__ w_ih,
                 const float* __restrict__ w_fx, const float* __restrict__ w_fh,
                 const float* __restrict__ w_ox, const float* __restrict__ w_oh,
                 const float* __restrict__ w_ph,
                 const float* __restrict__ b_g, const float* __restrict__ b_i,
                 const float* __restrict__ b_f, const float* __restrict__ b_o,
                 const float* __restrict__ b_p,
                 float* __restrict__ out)
{
    extern __shared__ char smc[];
    const u32 sbase = smem_u32(smc);
    float* sx  = (float*)(smc + SX_OFF);
    float* swx = (float*)(smc + SWX_OFF);
    float* sbg = (float*)(smc + SB_OFF);
    float* sbi = sbg + 128;
    float* sbf = sbi + 128;
    float* sbo = sbf + 128;

    const int tid   = threadIdx.x;
    const int bid   = blockIdx.x;
    const int ftile = bid & 31;           // 32 feature tiles of 16
    const int btile = bid >> 5;           // 4 batch tiles of 128
    const int F0    = ftile * FT;
    const int b0    = btile * BT;
    const int wid   = tid >> 5;           // warp 0..7: batch rows wid*16..+15
    const int lid   = tid & 31;
    const int tg    = lid & 3;
    const int q     = lid >> 2;

    __shared__ unsigned s_sense;
    if (tid == 0) s_sense = g_bar_sense;

    // ---- W resident in SMEM as bf16 hi+lo: B[n][k], n = 4*flocal + gate ----
    {
        const float* Wh[4] = {w_gh, w_ih, w_fh, w_oh};
        #pragma unroll 1
        for (int idx = tid; idx < NGATE * F_DIM; idx += THREADS) {
            const int n = idx >> 9;
            const int k = idx & 511;
            const int fl = n >> 2, gt = n & 3;
            const float v = Wh[gt][(F0 + fl) * F_DIM + k];
            const __nv_bfloat16 hi = __float2bfloat16(v);
            const __nv_bfloat16 lo = __float2bfloat16(v - __bfloat162float(hi));
            *(__nv_bfloat16*)(smc + BHI_OFF + ((u32)n * BST + (u32)k) * 2) = hi;
            *(__nv_bfloat16*)(smc + BLO_OFF + ((u32)n * BST + (u32)k) * 2) = lo;
        }
        if (tid < 64) {   // swx[4*fl+gt] = w_*x[F0+fl]
            const int fl = tid >> 2, gt = tid & 3;
            const float* Wx[4] = {w_gx, w_ix, w_fx, w_ox};
            swx[tid] = Wx[gt][F0 + fl];
        }
        // Reference quirk: gate biases broadcast along trailing (batch) axis.
        if (tid < 128) {
            sbg[tid] = b_g[b0 + tid];
            sbi[tid] = b_i[b0 + tid];
            sbf[tid] = b_f[b0 + tid];
            sbo[tid] = b_o[b0 + tid];
        }
    }

    // ---- Zero h plane 0 (grid covers exactly both planes, 1 uint4 each) ----
    {
        const int gidx = bid * THREADS + tid;            // 0..32767
        ((uint4*)g_hh[0])[gidx] = make_uint4(0u,0u,0u,0u);
        ((uint4*)g_hl[0])[gidx] = make_uint4(0u,0u,0u,0u);
    }
    __syncthreads();
    gsync(&s_sense);

    // ---- ldmatrix per-thread address offsets (bf16 elem units) ----
    // A (16x16 tile at warp rows): lanes 0-7 rows 0-7 k0-7; 8-15 rows 8-15;
    // 16-23 rows 0-7 k8-15; 24-31 rows 8-15 k8-15.
    const u32 a_off = (u32)(wid * 16 + (lid & 7) + 8 * ((lid >> 3) & 1)) * AST
                    + 8u * (u32)(lid >> 4);
    // B (n16 x k16 tile pair): lanes 0-7 n0-7 k0; 8-15 n0-7 k8; 16-23 n8-15 k0; 24-31 n8-15 k8
    const u32 b_off = (u32)((lid & 7) + 8 * (lid >> 4)) * BST + 8u * (u32)((lid >> 3) & 1);
    const u32 bhi_base = sbase + BHI_OFF + b_off * 2;
    const u32 blo_base = sbase + BLO_OFF + b_off * 2;

    float cst[16];
    #pragma unroll
    for (int i = 0; i < 16; ++i) cst[i] = 0.0f;

    for (int t = 0; t < L_DIM; ++t) {
        const __nv_bfloat16* __restrict__ srch = g_hh[t & 1];
        const __nv_bfloat16* __restrict__ srcl = g_hl[t & 1];
        const int dstp = (t & 1) ^ 1;

        if (tid < BT) sx[tid] = x[(size_t)(b0 + tid) * L_DIM + t];

        float acc[8][4];
        #pragma unroll
        for (int nt = 0; nt < 8; ++nt)
            #pragma unroll
            for (int j = 0; j < 4; ++j) acc[nt][j] = 0.0f;

        // prefetch chunk 0
        uint4 sthi[4], stlo[4];
        #pragma unroll
        for (int qq = 0; qq < 4; ++qq) {
            const int u = tid + qq * 256;
            const int row = u >> 3, seg = u & 7;
            const size_t e = (size_t)(b0 + row) * F_DIM + seg * 8;
            sthi[qq] = *(const uint4*)(srch + e);
            stlo[qq] = *(const uint4*)(srcl + e);
        }

        for (int c = 0; c < NCH; ++c) {
            const int p = c & 1;
            #pragma unroll
            for (int qq = 0; qq < 4; ++qq) {
                const int u = tid + qq * 256;
                const u32 so = ((u32)(u >> 3) * AST + (u32)(u & 7) * 8u) * 2u;
                *(uint4*)(smc + AHI_OFF(p) + so) = sthi[qq];
                *(uint4*)(smc + ALO_OFF(p) + so) = stlo[qq];
            }
            if (c < NCH - 1) {
                #pragma unroll
                for (int qq = 0; qq < 4; ++qq) {
                    const int u = tid + qq * 256;
                    const int row = u >> 3, seg = u & 7;
                    const size_t e = (size_t)(b0 + row) * F_DIM + (c + 1) * KC + seg * 8;
                    sthi[qq] = *(const uint4*)(srch + e);
                    stlo[qq] = *(const uint4*)(srcl + e);
                }
            }
            __syncthreads();

            const u32 ahi_a = sbase + AHI_OFF(p) + a_off * 2;
            const u32 alo_a = sbase + ALO_OFF(p) + a_off * 2;
            #pragma unroll
            for (int ks = 0; ks < 4; ++ks) {
                u32 Ahi[4], Alo[4];
                ldsm_x4(Ahi[0], Ahi[1], Ahi[2], Ahi[3], ahi_a + ks * 32);
                ldsm_x4(Alo[0], Alo[1], Alo[2], Alo[3], alo_a + ks * 32);
                const u32 koff = (u32)(c * KC + ks * 16) * 2;
                #pragma unroll
                for (int ntp = 0; ntp < 4; ++ntp) {
                    const u32 noff = (u32)(ntp * 16) * BST * 2;
                    u32 bh0, bh1, bh2, bh3, bl0, bl1, bl2, bl3;
                    ldsm_x4(bh0, bh1, bh2, bh3, bhi_base + noff + koff);
                    ldsm_x4(bl0, bl1, bl2, bl3, blo_base + noff + koff);
                    mma16816(acc[2*ntp],   Ahi, bh0, bh1);
                    mma16816(acc[2*ntp+1], Ahi, bh2, bh3);
                    mma16816(acc[2*ntp],   Ahi, bl0, bl1);
                    mma16816(acc[2*ntp+1], Ahi, bl2, bl3);
                    mma16816(acc[2*ntp],   Alo, bh0, bh1);
                    mma16816(acc[2*ntp+1], Alo, bh2, bh3);
                }
            }
        }

        // ---- Epilogue: gates live in lane pairs; one shfl.xor(1) joins them.
        // C frag: c0,c1 = (row q, cols 2tg,2tg+1); c2,c3 = (row q+8).
        // tg even lanes hold (g,i), odd hold (f,o) of feature 2nt+(tg>>1).
        const int floc2 = tg >> 1;
        #pragma unroll
        for (int nt = 0; nt < 8; ++nt) {
            const int floc = 2 * nt + floc2;
            const float wg_ = swx[4*floc + 0], wi_ = swx[4*floc + 1];
            const float wf_ = swx[4*floc + 2], wo_ = swx[4*floc + 3];
            #pragma unroll
            for (int rh = 0; rh < 2; ++rh) {
                const float m0 = acc[nt][rh*2 + 0];
                const float m1 = acc[nt][rh*2 + 1];
                const float o0 = __shfl_xor_sync(0xffffffffu, m0, 1);
                const float o1 = __shfl_xor_sync(0xffffffffu, m1, 1);
                const float vg = (tg & 1) ? o0 : m0;
                const float vi = (tg & 1) ? o1 : m1;
                const float vf = (tg & 1) ? m0 : o0;
                const float vo = (tg & 1) ? m1 : o1;
                const int row = wid * 16 + q + 8 * rh;
                const float xv = sx[row];
                const float pg = vg + wg_ * xv + sbg[row];
                const float pi = vi + wi_ * xv + sbi[row];
                const float pf = vf + wf_ * xv + sbf[row];
                const float po = vo + wo_ * xv + sbo[row];
                const float gg = tanh_acc(pg);
                const float si = sigm(pi);
                const float sf = sigm(pf);
                const float so = sigm(po);
                const float cn = gg * si + cst[nt*2 + rh] * sf;
                cst[nt*2 + rh] = cn;
                const float hv = tanh_acc(cn) * so;
                if (!(tg & 1)) {
                    const __nv_bfloat16 hi = __float2bfloat16(hv);
                    const __nv_bfloat16 lo = __float2bfloat16(hv - __bfloat162float(hi));
                    const size_t e = (size_t)(b0 + row) * F_DIM + F0 + floc;
                    g_hh[dstp][e] = hi;
                    g_hl[dstp][e] = lo;
                }
            }
        }
        gsync(&s_sense);
    }

    // ---- Projection: out[b][c] = sum_f h[b][f] * w_ph[f][c] + b_p[c] ----
    {
        const int c2 = (tid & 63) * 2;
        const int brow = bid * 4 + (tid >> 6);
        const __nv_bfloat16* __restrict__ hh = g_hh[0] + (size_t)brow * F_DIM;
        const __nv_bfloat16* __restrict__ hl = g_hl[0] + (size_t)brow * F_DIM;
        float a0 = 0.0f, a1 = 0.0f;
        #pragma unroll 4
        for (int f = 0; f < F_DIM; ++f) {
            const float hf = __bfloat162float(hh[f]) + __bfloat162float(hl[f]);
            a0 += hf * w_ph[f * C_DIM + c2];
            a1 += hf * w_ph[f * C_DIM + c2 + 1];
        }
        out[brow * C_DIM + c2]     = a0 + b_p[c2];
        out[brow * C_DIM + c2 + 1] = a1 + b_p[c2 + 1];
    }
}

extern "C" void kernel_launch(void* const* d_in, const int* in_sizes, int n_in,
                              void* d_out, int out_size)
{
    (void)in_sizes; (void)n_in; (void)out_size;
    const float* x    = (const float*)d_in[0];
    const float* w_gx = (const float*)d_in[1];
    const float* w_gh = (const float*)d_in[2];
    const float* w_ix = (const float*)d_in[3];
    const float* w_ih = (const float*)d_in[4];
    const float* w_fx = (const float*)d_in[5];
    const float* w_fh = (const float*)d_in[6];
    const float* w_ox = (const float*)d_in[7];
    const float* w_oh = (const float*)d_in[8];
    const float* w_ph = (const float*)d_in[9];
    const float* b_g  = (const float*)d_in[10];
    const float* b_i  = (const float*)d_in[11];
    const float* b_f  = (const float*)d_in[12];
    const float* b_o  = (const float*)d_in[13];
    const float* b_p  = (const float*)d_in[14];
    float* out = (float*)d_out;

    cudaFuncSetAttribute(lstm_hmma_kernel,
                         cudaFuncAttributeMaxDynamicSharedMemorySize, SMEM_TOTAL);

    lstm_hmma_kernel<<<GRID_BLOCKS, THREADS, SMEM_TOTAL>>>(
        x, w_gx, w_gh, w_ix, w_ih, w_fx, w_fh, w_ox, w_oh, w_ph,
        b_g, b_i, b_f, b_o, b_p, out);
}

// round 11
// speedup vs baseline: 1.9650x; 1.1919x over previous
#include <cuda_runtime.h>
#include <cuda_bf16.h>
#include <math.h>

typedef unsigned int u32;

#define F_DIM 512
#define B_DIM 512
#define L_DIM 256
#define C_DIM 128

#define GRID_BLOCKS 128
#define THREADS 256
#define FT    16      // features per CTA
#define NGATE 64      // gate cols per CTA (MMA N)
#define BT    128     // batch rows per CTA (MMA M)
#define KC    64      // k-chunk
#define NCH   8       // chunks per step

#define BST 520       // B row stride in bf16 (pad: conflict-free ldmatrix)
#define AST 72        // A row stride in bf16

// SMEM byte offsets
#define B_PLANE_BYTES (NGATE * BST * 2)          // 66560
#define BHI_OFF 0
#define BLO_OFF B_PLANE_BYTES
#define A_PLANE_BYTES (BT * AST * 2)             // 18432
#define A_OFF   (2 * B_PLANE_BYTES)              // 133120
#define AHI_OFF(p) (A_OFF + (p) * 2 * A_PLANE_BYTES)
#define ALO_OFF(p) (AHI_OFF(p) + A_PLANE_BYTES)
#define SX_OFF   (A_OFF + 4 * A_PLANE_BYTES)     // 206848 (128 floats)
#define SWX_OFF  (SX_OFF + 512)                  // 64 floats
#define SB_OFF   (SWX_OFF + 256)                 // 4 x 128 floats
#define SMEM_TOTAL (SB_OFF + 2048 + 64)          // ~209.8 KB

// Persistent device state
__device__ __nv_bfloat16 g_hh[2][B_DIM * F_DIM];   // h^T hi plane [batch][feat]
__device__ __nv_bfloat16 g_hl[2][B_DIM * F_DIM];   // h^T lo plane
// Per-btile-group barrier state (4 groups, 128B apart)
#define GRP_STRIDE 32
__device__ unsigned g_cnt[4 * GRP_STRIDE];
__device__ unsigned g_sense[4 * GRP_STRIDE];

__device__ __forceinline__ u32 smem_u32(const void* p) {
    u32 a; asm("{ .reg .u64 t; cvta.to.shared.u64 t, %1; cvt.u32.u64 %0, t; }" : "=r"(a) : "l"(p));
    return a;
}
__device__ __forceinline__ void ldsm_x4(u32& r0, u32& r1, u32& r2, u32& r3, u32 addr) {
    asm volatile("ldmatrix.sync.aligned.m8n8.x4.shared.b16 {%0,%1,%2,%3}, [%4];"
                 : "=r"(r0), "=r"(r1), "=r"(r2), "=r"(r3) : "r"(addr));
}
__device__ __forceinline__ void mma16816(float* c, const u32* a, u32 b0, u32 b1) {
    asm volatile("mma.sync.aligned.m16n8k16.row.col.f32.bf16.bf16.f32 "
                 "{%0,%1,%2,%3}, {%4,%5,%6,%7}, {%8,%9}, {%0,%1,%2,%3};"
                 : "+f"(c[0]), "+f"(c[1]), "+f"(c[2]), "+f"(c[3])
                 : "r"(a[0]), "r"(a[1]), "r"(a[2]), "r"(a[3]), "r"(b0), "r"(b1));
}

// sigmoid: ex2 + rcp (both MUFU, accurate to ~1e-6)
__device__ __forceinline__ float sigm(float x) {
    const float e = exp2f(-1.4426950408889634f * x);
    return 1.0f / (1.0f + e);
}
// tanh: single MUFU op (~5e-4 max err; recurrence contraction measured at
// ~0.1x makes this land ~4e-5 in the final output - 25x margin under 1e-3)
__device__ __forceinline__ float tanh_fast(float x) {
    float r; asm("tanh.approx.f32 %0, %1;" : "=f"(r) : "f"(x)); return r;
}

// Group barrier (32 CTAs sharing one btile). Release/acquire atomics:
// producers' h stores -> syncthreads -> thread0 atom.add.release (RMW chain
// forms release sequence) -> last arriver st.release sense -> waiters
// ld.acquire -> syncthreads. Replay-safe: initial sense read at kernel start.
__device__ __forceinline__ void gsync_grp(unsigned* s_sense, int grp) {
    __syncthreads();
    if (threadIdx.x == 0) {
        unsigned ns = *s_sense ^ 1u;
        *s_sense = ns;
        unsigned* cnt = &g_cnt[grp * GRP_STRIDE];
        unsigned* sen = &g_sense[grp * GRP_STRIDE];
        unsigned old;
        asm volatile("atom.release.gpu.global.add.u32 %0, [%1], %2;"
                     : "=r"(old) : "l"(cnt), "r"(1u) : "memory");
        if (old == 31u) {
            asm volatile("st.relaxed.gpu.global.u32 [%0], %1;" :: "l"(cnt), "r"(0u) : "memory");
            asm volatile("st.release.gpu.global.u32 [%0], %1;" :: "l"(sen), "r"(ns) : "memory");
        } else {
            unsigned v;
            do {
                asm volatile("ld.acquire.gpu.global.u32 %0, [%1];" : "=r"(v) : "l"(sen) : "memory");
            } while (v != ns);
        }
    }
    __syncthreads();
}

__global__ void __launch_bounds__(THREADS, 1)
lstm_hmma_kernel(const float* __restrict__ x,
                 const float* __restrict__ w_gx, const float* __restrict__ w_gh,
                 const float* __restrict__ w_ix, const float* __restrict__ w_ih,
                 const float* __restrict__ w_fx, const float* __restrict__ w_fh,
                 const float* __restrict__ w_ox, const float* __restrict__ w_oh,
                 const float* __restrict__ w_ph,
                 const float* __restrict__ b_g, const float* __restrict__ b_i,
                 const float* __restrict__ b_f, const float* __restrict__ b_o,
                 const float* __restrict__ b_p,
                 float* __restrict__ out)
{
    extern __shared__ char smc[];
    const u32 sbase = smem_u32(smc);
    float* sx  = (float*)(smc + SX_OFF);
    float* swx = (float*)(smc + SWX_OFF);
    float* sbg = (float*)(smc + SB_OFF);
    float* sbi = sbg + 128;
    float* sbf = sbi + 128;
    float* sbo = sbf + 128;

    const int tid   = threadIdx.x;
    const int bid   = blockIdx.x;
    const int ftile = bid & 31;           // 32 feature tiles of 16
    const int btile = bid >> 5;           // 4 batch tiles of 128 (= barrier group)
    const int F0    = ftile * FT;
    const int b0    = btile * BT;
    const int wid   = tid >> 5;           // warp 0..7: batch rows wid*16..+15
    const int lid   = tid & 31;
    const int tg    = lid & 3;
    const int q     = lid >> 2;

    __shared__ unsigned s_sense;
    if (tid == 0) s_sense = g_sense[btile * GRP_STRIDE];  // safe: our group can't flip yet

    // ---- W resident in SMEM as bf16 hi+lo: B[n][k], n = 4*flocal + gate ----
    {
        const float* Wh[4] = {w_gh, w_ih, w_fh, w_oh};
        #pragma unroll 1
        for (int idx = tid; idx < NGATE * F_DIM; idx += THREADS) {
            const int n = idx >> 9;
            const int k = idx & 511;
            const int fl = n >> 2, gt = n & 3;
            const float v = Wh[gt][(F0 + fl) * F_DIM + k];
            const __nv_bfloat16 hi = __float2bfloat16(v);
            const __nv_bfloat16 lo = __float2bfloat16(v - __bfloat162float(hi));
            *(__nv_bfloat16*)(smc + BHI_OFF + ((u32)n * BST + (u32)k) * 2) = hi;
            *(__nv_bfloat16*)(smc + BLO_OFF + ((u32)n * BST + (u32)k) * 2) = lo;
        }
        if (tid < 64) {   // swx[4*fl+gt] = w_*x[F0+fl]
            const int fl = tid >> 2, gt = tid & 3;
            const float* Wx[4] = {w_gx, w_ix, w_fx, w_ox};
            swx[tid] = Wx[gt][F0 + fl];
        }
        // Reference quirk: gate biases broadcast along trailing (batch) axis.
        if (tid < 128) {
            sbg[tid] = b_g[b0 + tid];
            sbi[tid] = b_i[b0 + tid];
            sbf[tid] = b_f[b0 + tid];
            sbo[tid] = b_o[b0 + tid];
        }
    }

    // ---- Zero h plane 0. CTA bid covers batch rows bid*4..+3 (own group). ----
    {
        const int gidx = bid * THREADS + tid;            // 0..32767
        ((uint4*)g_hh[0])[gidx] = make_uint4(0u,0u,0u,0u);
        ((uint4*)g_hl[0])[gidx] = make_uint4(0u,0u,0u,0u);
    }
    gsync_grp(&s_sense, btile);

    // ---- ldmatrix per-thread address offsets (bf16 elem units) ----
    const u32 a_off = (u32)(wid * 16 + (lid & 7) + 8 * ((lid >> 3) & 1)) * AST
                    + 8u * (u32)(lid >> 4);
    const u32 b_off = (u32)((lid & 7) + 8 * (lid >> 4)) * BST + 8u * (u32)((lid >> 3) & 1);
    const u32 bhi_base = sbase + BHI_OFF + b_off * 2;
    const u32 blo_base = sbase + BLO_OFF + b_off * 2;

    float cst[16];
    #pragma unroll
    for (int i = 0; i < 16; ++i) cst[i] = 0.0f;

    for (int t = 0; t < L_DIM; ++t) {
        const __nv_bfloat16* __restrict__ srch = g_hh[t & 1];
        const __nv_bfloat16* __restrict__ srcl = g_hl[t & 1];
        const int dstp = (t & 1) ^ 1;

        if (tid < BT) sx[tid] = x[(size_t)(b0 + tid) * L_DIM + t];

        float acc[8][4];
        #pragma unroll
        for (int nt = 0; nt < 8; ++nt)
            #pragma unroll
            for (int j = 0; j < 4; ++j) acc[nt][j] = 0.0f;

        // prefetch chunk 0
        uint4 sthi[4], stlo[4];
        #pragma unroll
        for (int qq = 0; qq < 4; ++qq) {
            const int u = tid + qq * 256;
            const int row = u >> 3, seg = u & 7;
            const size_t e = (size_t)(b0 + row) * F_DIM + seg * 8;
            sthi[qq] = *(const uint4*)(srch + e);
            stlo[qq] = *(const uint4*)(srcl + e);
        }

        for (int c = 0; c < NCH; ++c) {
            const int p = c & 1;
            #pragma unroll
            for (int qq = 0; qq < 4; ++qq) {
                const int u = tid + qq * 256;
                const u32 so = ((u32)(u >> 3) * AST + (u32)(u & 7) * 8u) * 2u;
                *(uint4*)(smc + AHI_OFF(p) + so) = sthi[qq];
                *(uint4*)(smc + ALO_OFF(p) + so) = stlo[qq];
            }
            if (c < NCH - 1) {
                #pragma unroll
                for (int qq = 0; qq < 4; ++qq) {
                    const int u = tid + qq * 256;
                    const int row = u >> 3, seg = u & 7;
                    const size_t e = (size_t)(b0 + row) * F_DIM + (c + 1) * KC + seg * 8;
                    sthi[qq] = *(const uint4*)(srch + e);
                    stlo[qq] = *(const uint4*)(srcl + e);
                }
            }
            __syncthreads();

            const u32 ahi_a = sbase + AHI_OFF(p) + a_off * 2;
            const u32 alo_a = sbase + ALO_OFF(p) + a_off * 2;
            #pragma unroll
            for (int ks = 0; ks < 4; ++ks) {
                u32 Ahi[4], Alo[4];
                ldsm_x4(Ahi[0], Ahi[1], Ahi[2], Ahi[3], ahi_a + ks * 32);
                ldsm_x4(Alo[0], Alo[1], Alo[2], Alo[3], alo_a + ks * 32);
                const u32 koff = (u32)(c * KC + ks * 16) * 2;
                #pragma unroll
                for (int ntp = 0; ntp < 4; ++ntp) {
                    const u32 noff = (u32)(ntp * 16) * BST * 2;
                    u32 bh0, bh1, bh2, bh3, bl0, bl1, bl2, bl3;
                    ldsm_x4(bh0, bh1, bh2, bh3, bhi_base + noff + koff);
                    ldsm_x4(bl0, bl1, bl2, bl3, blo_base + noff + koff);
                    mma16816(acc[2*ntp],   Ahi, bh0, bh1);
                    mma16816(acc[2*ntp+1], Ahi, bh2, bh3);
                    mma16816(acc[2*ntp],   Ahi, bl0, bl1);
                    mma16816(acc[2*ntp+1], Ahi, bl2, bl3);
                    mma16816(acc[2*ntp],   Alo, bh0, bh1);
                    mma16816(acc[2*ntp+1], Alo, bh2, bh3);
                }
            }
        }

        // ---- Epilogue: gates live in lane pairs; one shfl.xor(1) joins them.
        const int floc2 = tg >> 1;
        #pragma unroll
        for (int nt = 0; nt < 8; ++nt) {
            const int floc = 2 * nt + floc2;
            const float wg_ = swx[4*floc + 0], wi_ = swx[4*floc + 1];
            const float wf_ = swx[4*floc + 2], wo_ = swx[4*floc + 3];
            #pragma unroll
            for (int rh = 0; rh < 2; ++rh) {
                const float m0 = acc[nt][rh*2 + 0];
                const float m1 = acc[nt][rh*2 + 1];
                const float o0 = __shfl_xor_sync(0xffffffffu, m0, 1);
                const float o1 = __shfl_xor_sync(0xffffffffu, m1, 1);
                const float vg = (tg & 1) ? o0 : m0;
                const float vi = (tg & 1) ? o1 : m1;
                const float vf = (tg & 1) ? m0 : o0;
                const float vo = (tg & 1) ? m1 : o1;
                const int row = wid * 16 + q + 8 * rh;
                const float xv = sx[row];
                const float pg = vg + wg_ * xv + sbg[row];
                const float pi = vi + wi_ * xv + sbi[row];
                const float pf = vf + wf_ * xv + sbf[row];
                const float po = vo + wo_ * xv + sbo[row];
                const float gg = tanh_fast(pg);
                const float si = sigm(pi);
                const float sf = sigm(pf);
                const float so = sigm(po);
                const float cn = gg * si + cst[nt*2 + rh] * sf;
                cst[nt*2 + rh] = cn;
                const float hv = tanh_fast(cn) * so;
                if (!(tg & 1)) {
                    const __nv_bfloat16 hi = __float2bfloat16(hv);
                    const __nv_bfloat16 lo = __float2bfloat16(hv - __bfloat162float(hi));
                    const size_t e = (size_t)(b0 + row) * F_DIM + F0 + floc;
                    g_hh[dstp][e] = hi;
                    g_hl[dstp][e] = lo;
                }
            }
        }
        gsync_grp(&s_sense, btile);
    }

    // ---- Projection: out[b][c] = sum_f h[b][f] * w_ph[f][c] + b_p[c] ----
    // CTA bid reads batch rows bid*4..+3 (own group; ordered by final gsync).
    {
        const int c2 = (tid & 63) * 2;
        const int brow = bid * 4 + (tid >> 6);
        const __nv_bfloat16* __restrict__ hh = g_hh[0] + (size_t)brow * F_DIM;
        const __nv_bfloat16* __restrict__ hl = g_hl[0] + (size_t)brow * F_DIM;
        float a0 = 0.0f, a1 = 0.0f;
        #pragma unroll 4
        for (int f = 0; f < F_DIM; ++f) {
            const float hf = __bfloat162float(hh[f]) + __bfloat162float(hl[f]);
            a0 += hf * w_ph[f * C_DIM + c2];
            a1 += hf * w_ph[f * C_DIM + c2 + 1];
        }
        out[brow * C_DIM + c2]     = a0 + b_p[c2];
        out[brow * C_DIM + c2 + 1] = a1 + b_p[c2 + 1];
    }
}

extern "C" void kernel_launch(void* const* d_in, const int* in_sizes, int n_in,
                              void* d_out, int out_size)
{
    (void)in_sizes; (void)n_in; (void)out_size;
    const float* x    = (const float*)d_in[0];
    const float* w_gx = (const float*)d_in[1];
    const float* w_gh = (const float*)d_in[2];
    const float* w_ix = (const float*)d_in[3];
    const float* w_ih = (const float*)d_in[4];
    const float* w_fx = (const float*)d_in[5];
    const float* w_fh = (const float*)d_in[6];
    const float* w_ox = (const float*)d_in[7];
    const float* w_oh = (const float*)d_in[8];
    const float* w_ph = (const float*)d_in[9];
    const float* b_g  = (const float*)d_in[10];
    const float* b_i  = (const float*)d_in[11];
    const float* b_f  = (const float*)d_in[12];
    const float* b_o  = (const float*)d_in[13];
    const float* b_p  = (const float*)d_in[14];
    float* out = (float*)d_out;

    cudaFuncSetAttribute(lstm_hmma_kernel,
                         cudaFuncAttributeMaxDynamicSharedMemorySize, SMEM_TOTAL);

    lstm_hmma_kernel<<<GRID_BLOCKS, THREADS, SMEM_TOTAL>>>(
        x, w_gx, w_gh, w_ix, w_ih, w_fx, w_fh, w_ox, w_oh, w_ph,
        b_g, b_i, b_f, b_o, b_p, out);
}

// round 12
// speedup vs baseline: 2.4873x; 1.2658x over previous
#include <cuda_runtime.h>
#include <cuda_fp16.h>
#include <math.h>

typedef unsigned int u32;

#define F_DIM 512
#define B_DIM 512
#define L_DIM 256
#define C_DIM 128

#define GRID_BLOCKS 128
#define THREADS 256
#define FT    16      // features per CTA
#define NGATE 64      // gate cols per CTA (MMA N)
#define BT    128     // batch rows per CTA (MMA M)
#define KC    64      // k-chunk
#define NCH   8       // chunks per step

#define BST 520       // B row stride in fp16 (pad: conflict-free ldmatrix)
#define AST 72        // A row stride in fp16

// SMEM byte offsets
#define B_PLANE_BYTES (NGATE * BST * 2)          // 66560
#define BHI_OFF 0
#define BLO_OFF B_PLANE_BYTES
#define A_PLANE_BYTES (BT * AST * 2)             // 18432
#define A_OFF   (2 * B_PLANE_BYTES)              // 133120
#define ABUF(p) (A_OFF + (p) * A_PLANE_BYTES)
#define SX_OFF   (A_OFF + 2 * A_PLANE_BYTES)     // 169984 (128 floats)
#define SWX_OFF  (SX_OFF + 512)                  // 64 floats
#define SB_OFF   (SWX_OFF + 256)                 // 4 x 128 floats
#define SMEM_TOTAL (SB_OFF + 2048 + 64)          // ~172.9 KB

// Persistent device state: h as single fp16 plane [batch][feat]
__device__ __half g_h[2][B_DIM * F_DIM];
// Per-btile-group barrier state (4 groups, 128B apart)
#define GRP_STRIDE 32
__device__ unsigned g_cnt[4 * GRP_STRIDE];
__device__ unsigned g_sense[4 * GRP_STRIDE];

__device__ __forceinline__ u32 smem_u32(const void* p) {
    u32 a; asm("{ .reg .u64 t; cvta.to.shared.u64 t, %1; cvt.u32.u64 %0, t; }" : "=r"(a) : "l"(p));
    return a;
}
__device__ __forceinline__ void ldsm_x4(u32& r0, u32& r1, u32& r2, u32& r3, u32 addr) {
    asm volatile("ldmatrix.sync.aligned.m8n8.x4.shared.b16 {%0,%1,%2,%3}, [%4];"
                 : "=r"(r0), "=r"(r1), "=r"(r2), "=r"(r3) : "r"(addr));
}
__device__ __forceinline__ void mma16816h(float* c, const u32* a, u32 b0, u32 b1) {
    asm volatile("mma.sync.aligned.m16n8k16.row.col.f32.f16.f16.f32 "
                 "{%0,%1,%2,%3}, {%4,%5,%6,%7}, {%8,%9}, {%0,%1,%2,%3};"
                 : "+f"(c[0]), "+f"(c[1]), "+f"(c[2]), "+f"(c[3])
                 : "r"(a[0]), "r"(a[1]), "r"(a[2]), "r"(a[3]), "r"(b0), "r"(b1));
}

__device__ __forceinline__ float sigm(float x) {
    const float e = exp2f(-1.4426950408889634f * x);
    return 1.0f / (1.0f + e);
}
__device__ __forceinline__ float tanh_fast(float x) {
    float r; asm("tanh.approx.f32 %0, %1;" : "=f"(r) : "f"(x)); return r;
}

// Group barrier (32 CTAs sharing one btile), release/acquire atomics.
__device__ __forceinline__ void gsync_grp(unsigned* s_sense, int grp) {
    __syncthreads();
    if (threadIdx.x == 0) {
        unsigned ns = *s_sense ^ 1u;
        *s_sense = ns;
        unsigned* cnt = &g_cnt[grp * GRP_STRIDE];
        unsigned* sen = &g_sense[grp * GRP_STRIDE];
        unsigned old;
        asm volatile("atom.release.gpu.global.add.u32 %0, [%1], %2;"
                     : "=r"(old) : "l"(cnt), "r"(1u) : "memory");
        if (old == 31u) {
            asm volatile("st.relaxed.gpu.global.u32 [%0], %1;" :: "l"(cnt), "r"(0u) : "memory");
            asm volatile("st.release.gpu.global.u32 [%0], %1;" :: "l"(sen), "r"(ns) : "memory");
        } else {
            unsigned v;
            do {
                asm volatile("ld.acquire.gpu.global.u32 %0, [%1];" : "=r"(v) : "l"(sen) : "memory");
            } while (v != ns);
        }
    }
    __syncthreads();
}

__global__ void __launch_bounds__(THREADS, 1)
lstm_hmma_kernel(const float* __restrict__ x,
                 const float* __restrict__ w_gx, const float* __restrict__ w_gh,
                 const float* __restrict__ w_ix, const float* __restrict__ w_ih,
                 const float* __restrict__ w_fx, const float* __restrict__ w_fh,
                 const float* __restrict__ w_ox, const float* __restrict__ w_oh,
                 const float* __restrict__ w_ph,
                 const float* __restrict__ b_g, const float* __restrict__ b_i,
                 const float* __restrict__ b_f, const float* __restrict__ b_o,
                 const float* __restrict__ b_p,
                 float* __restrict__ out)
{
    extern __shared__ char smc[];
    const u32 sbase = smem_u32(smc);
    float* sx  = (float*)(smc + SX_OFF);
    float* swx = (float*)(smc + SWX_OFF);
    float* sbg = (float*)(smc + SB_OFF);
    float* sbi = sbg + 128;
    float* sbf = sbi + 128;
    float* sbo = sbf + 128;

    const int tid   = threadIdx.x;
    const int bid   = blockIdx.x;
    const int ftile = bid & 31;
    const int btile = bid >> 5;
    const int F0    = ftile * FT;
    const int b0    = btile * BT;
    const int wid   = tid >> 5;
    const int lid   = tid & 31;
    const int wm    = wid >> 1;           // 0..3: batch rows wm*32..+31
    const int wn    = wid & 1;            // 0..1: gates wn*32..+31 (features 8wn..+7)
    const int tg    = lid & 3;
    const int q     = lid >> 2;

    __shared__ unsigned s_sense;
    if (tid == 0) s_sense = g_sense[btile * GRP_STRIDE];

    // ---- W resident in SMEM: fp16 hi plane + fp16 (lo*2048) plane ----
    {
        const float* Wh[4] = {w_gh, w_ih, w_fh, w_oh};
        #pragma unroll 1
        for (int idx = tid; idx < NGATE * F_DIM; idx += THREADS) {
            const int n = idx >> 9;
            const int k = idx & 511;
            const int fl = n >> 2, gt = n & 3;
            const float v = Wh[gt][(F0 + fl) * F_DIM + k];
            const __half hi = __float2half(v);
            const __half lo = __float2half((v - __half2float(hi)) * 2048.0f);
            *(__half*)(smc + BHI_OFF + ((u32)n * BST + (u32)k) * 2) = hi;
            *(__half*)(smc + BLO_OFF + ((u32)n * BST + (u32)k) * 2) = lo;
        }
        if (tid < 64) {
            const int fl = tid >> 2, gt = tid & 3;
            const float* Wx[4] = {w_gx, w_ix, w_fx, w_ox};
            swx[tid] = Wx[gt][F0 + fl];
        }
        // Reference quirk: gate biases broadcast along trailing (batch) axis.
        if (tid < 128) {
            sbg[tid] = b_g[b0 + tid];
            sbi[tid] = b_i[b0 + tid];
            sbf[tid] = b_f[b0 + tid];
            sbo[tid] = b_o[b0 + tid];
        }
    }

    // ---- Zero h plane 0: grid covers plane exactly (1 uint4 per thread) ----
    {
        const int gidx = bid * THREADS + tid;            // 0..32767
        ((uint4*)g_h[0])[gidx] = make_uint4(0u,0u,0u,0u);
    }
    gsync_grp(&s_sense, btile);

    // ---- ldmatrix per-thread byte offsets ----
    // A tiles: rows wm*32 + mt*16 + (lid&7) + 8*((lid>>3)&1), col 8*(lid>>4)
    const u32 a_off0 = (((u32)(wm * 32 + (lid & 7) + 8 * ((lid >> 3) & 1))) * AST
                       + 8u * (u32)(lid >> 4)) * 2u;
    // B tiles: rows wn*32 + ntp*16 + (lid&7) + 8*(lid>>4), col 8*((lid>>3)&1)
    const u32 b_off0 = (((u32)(wn * 32 + (lid & 7) + 8 * (lid >> 4))) * BST
                       + 8u * (u32)((lid >> 3) & 1)) * 2u;
    const u32 bhi_base = sbase + BHI_OFF + b_off0;
    const u32 blo_base = sbase + BLO_OFF + b_off0;

    float cst[16];                 // [mt*2+rh][nt]
    #pragma unroll
    for (int i = 0; i < 16; ++i) cst[i] = 0.0f;

    for (int t = 0; t < L_DIM; ++t) {
        const __half* __restrict__ srch = g_h[t & 1];
        const int dstp = (t & 1) ^ 1;

        if (tid < BT) sx[tid] = x[(size_t)(b0 + tid) * L_DIM + t];

        float acc [2][4][4];       // hi-W term
        float accL[2][4][4];       // lo-W term (scaled by 2048)
        #pragma unroll
        for (int mt = 0; mt < 2; ++mt)
            #pragma unroll
            for (int nt = 0; nt < 4; ++nt)
                #pragma unroll
                for (int j = 0; j < 4; ++j) { acc[mt][nt][j] = 0.0f; accL[mt][nt][j] = 0.0f; }

        // prefetch chunk 0: A = h[b0..b0+127][c*64..+63] fp16 (4 uint4/thread)
        uint4 st[4];
        #pragma unroll
        for (int qq = 0; qq < 4; ++qq) {
            const int u = tid + qq * 256;
            const int row = u >> 3, seg = u & 7;
            st[qq] = *(const uint4*)(srch + (size_t)(b0 + row) * F_DIM + seg * 8);
        }

        for (int c = 0; c < NCH; ++c) {
            const int p = c & 1;
            #pragma unroll
            for (int qq = 0; qq < 4; ++qq) {
                const int u = tid + qq * 256;
                const u32 so = ((u32)(u >> 3) * AST + (u32)(u & 7) * 8u) * 2u;
                *(uint4*)(smc + ABUF(p) + so) = st[qq];
            }
            if (c < NCH - 1) {
                #pragma unroll
                for (int qq = 0; qq < 4; ++qq) {
                    const int u = tid + qq * 256;
                    const int row = u >> 3, seg = u & 7;
                    st[qq] = *(const uint4*)(srch + (size_t)(b0 + row) * F_DIM
                                             + (c + 1) * KC + seg * 8);
                }
            }
            __syncthreads();

            const u32 a_base = sbase + ABUF(p) + a_off0;
            #pragma unroll
            for (int ks = 0; ks < 4; ++ks) {
                u32 A0[4], A1[4];
                ldsm_x4(A0[0], A0[1], A0[2], A0[3], a_base + ks * 32);
                ldsm_x4(A1[0], A1[1], A1[2], A1[3], a_base + ks * 32 + 16 * AST * 2);
                const u32 koff = (u32)(c * KC + ks * 16) * 2;
                #pragma unroll
                for (int ntp = 0; ntp < 2; ++ntp) {
                    const u32 noff = (u32)(ntp * 16) * BST * 2;
                    u32 bh0, bh1, bh2, bh3, bl0, bl1, bl2, bl3;
                    ldsm_x4(bh0, bh1, bh2, bh3, bhi_base + noff + koff);
                    ldsm_x4(bl0, bl1, bl2, bl3, blo_base + noff + koff);
                    mma16816h(acc [0][2*ntp],   A0, bh0, bh1);
                    mma16816h(acc [0][2*ntp+1], A0, bh2, bh3);
                    mma16816h(acc [1][2*ntp],   A1, bh0, bh1);
                    mma16816h(acc [1][2*ntp+1], A1, bh2, bh3);
                    mma16816h(accL[0][2*ntp],   A0, bl0, bl1);
                    mma16816h(accL[0][2*ntp+1], A0, bl2, bl3);
                    mma16816h(accL[1][2*ntp],   A1, bl0, bl1);
                    mma16816h(accL[1][2*ntp+1], A1, bl2, bl3);
                }
            }
        }

        // ---- Epilogue: combine hi + lo/2048; gates in lane pairs (shfl.xor 1)
        const float INV2048 = 4.8828125e-4f;
        #pragma unroll
        for (int mt = 0; mt < 2; ++mt) {
            #pragma unroll
            for (int nt = 0; nt < 4; ++nt) {
                const int floc = 8 * wn + 2 * nt + (tg >> 1);
                const float wg_ = swx[4*floc + 0], wi_ = swx[4*floc + 1];
                const float wf_ = swx[4*floc + 2], wo_ = swx[4*floc + 3];
                #pragma unroll
                for (int rh = 0; rh < 2; ++rh) {
                    const float m0 = acc[mt][nt][rh*2 + 0] + accL[mt][nt][rh*2 + 0] * INV2048;
                    const float m1 = acc[mt][nt][rh*2 + 1] + accL[mt][nt][rh*2 + 1] * INV2048;
                    const float o0 = __shfl_xor_sync(0xffffffffu, m0, 1);
                    const float o1 = __shfl_xor_sync(0xffffffffu, m1, 1);
                    const float vg = (tg & 1) ? o0 : m0;
                    const float vi = (tg & 1) ? o1 : m1;
                    const float vf = (tg & 1) ? m0 : o0;
                    const float vo = (tg & 1) ? m1 : o1;
                    const int row = wm * 32 + mt * 16 + q + 8 * rh;
                    const float xv = sx[row];
                    const float pg = vg + wg_ * xv + sbg[row];
                    const float pi = vi + wi_ * xv + sbi[row];
                    const float pf = vf + wf_ * xv + sbf[row];
                    const float po = vo + wo_ * xv + sbo[row];
                    const float gg = tanh_fast(pg);
                    const float si = sigm(pi);
                    const float sf = sigm(pf);
                    const float so = sigm(po);
                    const int ci = (mt * 2 + rh) * 4 + nt;
                    const float cn = gg * si + cst[ci] * sf;
                    cst[ci] = cn;
                    const float hv = tanh_fast(cn) * so;
                    if (!(tg & 1)) {
                        g_h[dstp][(size_t)(b0 + row) * F_DIM + F0 + floc] = __float2half(hv);
                    }
                }
            }
        }
        gsync_grp(&s_sense, btile);
    }

    // ---- Projection: out[b][c] = sum_f h[b][f] * w_ph[f][c] + b_p[c] ----
    {
        const int c2 = (tid & 63) * 2;
        const int brow = bid * 4 + (tid >> 6);
        const __half* __restrict__ hh = g_h[0] + (size_t)brow * F_DIM;
        float a0 = 0.0f, a1 = 0.0f;
        #pragma unroll 4
        for (int f = 0; f < F_DIM; ++f) {
            const float hf = __half2float(hh[f]);
            a0 += hf * w_ph[f * C_DIM + c2];
            a1 += hf * w_ph[f * C_DIM + c2 + 1];
        }
        out[brow * C_DIM + c2]     = a0 + b_p[c2];
        out[brow * C_DIM + c2 + 1] = a1 + b_p[c2 + 1];
    }
}

extern "C" void kernel_launch(void* const* d_in, const int* in_sizes, int n_in,
                              void* d_out, int out_size)
{
    (void)in_sizes; (void)n_in; (void)out_size;
    const float* x    = (const float*)d_in[0];
    const float* w_gx = (const float*)d_in[1];
    const float* w_gh = (const float*)d_in[2];
    const float* w_ix = (const float*)d_in[3];
    const float* w_ih = (const float*)d_in[4];
    const float* w_fx = (const float*)d_in[5];
    const float* w_fh = (const float*)d_in[6];
    const float* w_ox = (const float*)d_in[7];
    const float* w_oh = (const float*)d_in[8];
    const float* w_ph = (const float*)d_in[9];
    const float* b_g  = (const float*)d_in[10];
    const float* b_i  = (const float*)d_in[11];
    const float* b_f  = (const float*)d_in[12];
    const float* b_o  = (const float*)d_in[13];
    const float* b_p  = (const float*)d_in[14];
    float* out = (float*)d_out;

    cudaFuncSetAttribute(lstm_hmma_kernel,
                         cudaFuncAttributeMaxDynamicSharedMemorySize, SMEM_TOTAL);

    lstm_hmma_kernel<<<GRID_BLOCKS, THREADS, SMEM_TOTAL>>>(
        x, w_gx, w_gh, w_ix, w_ih, w_fx, w_fh, w_ox, w_oh, w_ph,
        b_g, b_i, b_f, b_o, b_p, out);
}

// round 13
// speedup vs baseline: 2.8426x; 1.1429x over previous
#include <cuda_runtime.h>
#include <cuda_fp16.h>
#include <math.h>

typedef unsigned int u32;

#define F_DIM 512
#define B_DIM 512
#define L_DIM 256
#define C_DIM 128

#define GRID_BLOCKS 128
#define THREADS 256
#define FT    16      // features per CTA
#define NGATE 64      // gate cols per CTA (MMA N)
#define BT    128     // batch rows per CTA (MMA M)
#define KC    64      // k-chunk
#define NCH   8       // chunks per step

#define BST 520       // B row stride in fp16 (pad: conflict-free ldmatrix)
#define AST 72        // A row stride in fp16

// SMEM byte offsets
#define B_PLANE_BYTES (NGATE * BST * 2)          // 66560 (1024-aligned)
#define BHI_OFF 0
#define A_PLANE_BYTES (BT * AST * 2)             // 18432
#define A_OFF   B_PLANE_BYTES
#define ABUF(p) (A_OFF + (p) * A_PLANE_BYTES)
#define SX_OFF   (A_OFF + 2 * A_PLANE_BYTES)     // 103424 (128 floats)
#define SWX_OFF  (SX_OFF + 512)                  // 64 floats
#define SB_OFF   (SWX_OFF + 256)                 // 4 x 128 floats
#define SMEM_TOTAL (SB_OFF + 2048 + 64)          // ~106 KB

// Persistent device state: h as single fp16 plane [batch][feat]
__device__ __half g_h[2][B_DIM * F_DIM];
// Full-group barrier state (4 groups) - used only at init and teardown
#define GRP_STRIDE 32
__device__ unsigned g_cnt[4 * GRP_STRIDE];
__device__ unsigned g_sense[4 * GRP_STRIDE];
// Per-chunk monotonic counters: g_ck[(grp*8 + c)*32]; producer (4 CTAs per
// chunk) release-increments once per step; consumer waits >= 4*t.
#define CKS 32
__device__ unsigned g_ck[4 * 8 * CKS];

__device__ __forceinline__ u32 smem_u32(const void* p) {
    u32 a; asm("{ .reg .u64 t; cvta.to.shared.u64 t, %1; cvt.u32.u64 %0, t; }" : "=r"(a) : "l"(p));
    return a;
}
__device__ __forceinline__ void ldsm_x4(u32& r0, u32& r1, u32& r2, u32& r3, u32 addr) {
    asm volatile("ldmatrix.sync.aligned.m8n8.x4.shared.b16 {%0,%1,%2,%3}, [%4];"
                 : "=r"(r0), "=r"(r1), "=r"(r2), "=r"(r3) : "r"(addr));
}
__device__ __forceinline__ void mma16816h(float* c, const u32* a, u32 b0, u32 b1) {
    asm volatile("mma.sync.aligned.m16n8k16.row.col.f32.f16.f16.f32 "
                 "{%0,%1,%2,%3}, {%4,%5,%6,%7}, {%8,%9}, {%0,%1,%2,%3};"
                 : "+f"(c[0]), "+f"(c[1]), "+f"(c[2]), "+f"(c[3])
                 : "r"(a[0]), "r"(a[1]), "r"(a[2]), "r"(a[3]), "r"(b0), "r"(b1));
}
__device__ __forceinline__ u32 ld_acq(const unsigned* p) {
    u32 v; asm volatile("ld.acquire.gpu.global.u32 %0, [%1];" : "=r"(v) : "l"(p) : "memory");
    return v;
}

__device__ __forceinline__ float sigm(float x) {
    const float e = exp2f(-1.4426950408889634f * x);
    return 1.0f / (1.0f + e);
}
__device__ __forceinline__ float tanh_fast(float x) {
    float r; asm("tanh.approx.f32 %0, %1;" : "=f"(r) : "f"(x)); return r;
}

// Full group barrier (32 CTAs of one btile) - init/teardown only.
__device__ __forceinline__ void gsync_grp(unsigned* s_sense, int grp) {
    __syncthreads();
    if (threadIdx.x == 0) {
        unsigned ns = *s_sense ^ 1u;
        *s_sense = ns;
        unsigned* cnt = &g_cnt[grp * GRP_STRIDE];
        unsigned* sen = &g_sense[grp * GRP_STRIDE];
        unsigned old;
        asm volatile("atom.release.gpu.global.add.u32 %0, [%1], %2;"
                     : "=r"(old) : "l"(cnt), "r"(1u) : "memory");
        if (old == 31u) {
            asm volatile("st.relaxed.gpu.global.u32 [%0], %1;" :: "l"(cnt), "r"(0u) : "memory");
            asm volatile("st.release.gpu.global.u32 [%0], %1;" :: "l"(sen), "r"(ns) : "memory");
        } else {
            unsigned v;
            do {
                asm volatile("ld.acquire.gpu.global.u32 %0, [%1];" : "=r"(v) : "l"(sen) : "memory");
            } while (v != ns);
        }
    }
    __syncthreads();
}

__global__ void __launch_bounds__(THREADS, 1)
lstm_hmma_kernel(const float* __restrict__ x,
                 const float* __restrict__ w_gx, const float* __restrict__ w_gh,
                 const float* __restrict__ w_ix, const float* __restrict__ w_ih,
                 const float* __restrict__ w_fx, const float* __restrict__ w_fh,
                 const float* __restrict__ w_ox, const float* __restrict__ w_oh,
                 const float* __restrict__ w_ph,
                 const float* __restrict__ b_g, const float* __restrict__ b_i,
                 const float* __restrict__ b_f, const float* __restrict__ b_o,
                 const float* __restrict__ b_p,
                 float* __restrict__ out)
{
    extern __shared__ char smc[];
    const u32 sbase = smem_u32(smc);
    float* sx  = (float*)(smc + SX_OFF);
    float* swx = (float*)(smc + SWX_OFF);
    float* sbg = (float*)(smc + SB_OFF);
    float* sbi = sbg + 128;
    float* sbf = sbi + 128;
    float* sbo = sbf + 128;

    const int tid   = threadIdx.x;
    const int bid   = blockIdx.x;
    const int ftile = bid & 31;
    const int btile = bid >> 5;
    const int F0    = ftile * FT;
    const int b0    = btile * BT;
    const int wid   = tid >> 5;
    const int lid   = tid & 31;
    const int wm    = wid >> 1;           // 0..3: batch rows wm*32..+31
    const int wn    = wid & 1;            // 0..1: gates wn*32..+31 (features 8wn..+7)
    const int tg    = lid & 3;
    const int q     = lid >> 2;
    const int mychunk = ftile >> 2;       // chunk this CTA's features belong to

    __shared__ unsigned s_sense;
    if (tid == 0) s_sense = g_sense[btile * GRP_STRIDE];

    unsigned* ckbase = &g_ck[(btile * 8) * CKS];
    unsigned* my_ck  = &g_ck[(btile * 8 + mychunk) * CKS];

    // ---- W resident in SMEM: single fp16 plane ----
    {
        const float* Wh[4] = {w_gh, w_ih, w_fh, w_oh};
        #pragma unroll 1
        for (int idx = tid; idx < NGATE * F_DIM; idx += THREADS) {
            const int n = idx >> 9;
            const int k = idx & 511;
            const int fl = n >> 2, gt = n & 3;
            const float v = Wh[gt][(F0 + fl) * F_DIM + k];
            *(__half*)(smc + BHI_OFF + ((u32)n * BST + (u32)k) * 2) = __float2half(v);
        }
        if (tid < 64) {
            const int fl = tid >> 2, gt = tid & 3;
            const float* Wx[4] = {w_gx, w_ix, w_fx, w_ox};
            swx[tid] = Wx[gt][F0 + fl];
        }
        // Reference quirk: gate biases broadcast along trailing (batch) axis.
        if (tid < 128) {
            sbg[tid] = b_g[b0 + tid];
            sbi[tid] = b_i[b0 + tid];
            sbf[tid] = b_f[b0 + tid];
            sbo[tid] = b_o[b0 + tid];
        }
    }

    // ---- Zero h plane 0 ----
    {
        const int gidx = bid * THREADS + tid;
        ((uint4*)g_h[0])[gidx] = make_uint4(0u,0u,0u,0u);
    }
    gsync_grp(&s_sense, btile);

    // ---- ldmatrix per-thread byte offsets ----
    const u32 a_off0 = (((u32)(wm * 32 + (lid & 7) + 8 * ((lid >> 3) & 1))) * AST
                       + 8u * (u32)(lid >> 4)) * 2u;
    const u32 b_off0 = (((u32)(wn * 32 + (lid & 7) + 8 * (lid >> 4))) * BST
                       + 8u * (u32)((lid >> 3) & 1)) * 2u;
    const u32 bhi_base = sbase + BHI_OFF + b_off0;

    float cst[16];
    #pragma unroll
    for (int i = 0; i < 16; ++i) cst[i] = 0.0f;

    for (int t = 0; t < L_DIM; ++t) {
        const __half* __restrict__ srch = g_h[t & 1];
        const int dstp = (t & 1) ^ 1;
        const u32 thr = 4u * (u32)t;      // producers arrived t times each

        if (tid < BT) sx[tid] = x[(size_t)(b0 + tid) * L_DIM + t];

        float acc[2][4][4];
        #pragma unroll
        for (int mt = 0; mt < 2; ++mt)
            #pragma unroll
            for (int nt = 0; nt < 4; ++nt)
                #pragma unroll
                for (int j = 0; j < 4; ++j) acc[mt][nt][j] = 0.0f;

        // hard wait for chunk 0 producers, then prefetch chunk 0
        while (ld_acq(ckbase + 0 * CKS) < thr) {}
        uint4 st[4];
        #pragma unroll
        for (int qq = 0; qq < 4; ++qq) {
            const int u = tid + qq * 256;
            const int row = u >> 3, seg = u & 7;
            st[qq] = *(const uint4*)(srch + (size_t)(b0 + row) * F_DIM + seg * 8);
        }
        // speculative poll for chunk 1 (verified at c=0)
        u32 pv = ld_acq(ckbase + 1 * CKS);

        for (int c = 0; c < NCH; ++c) {
            const int p = c & 1;
            #pragma unroll
            for (int qq = 0; qq < 4; ++qq) {
                const int u = tid + qq * 256;
                const u32 so = ((u32)(u >> 3) * AST + (u32)(u & 7) * 8u) * 2u;
                *(uint4*)(smc + ABUF(p) + so) = st[qq];
            }
            if (c < NCH - 1) {
                // verify chunk c+1 ready (poll was issued one iteration ago)
                while (pv < thr) pv = ld_acq(ckbase + (c + 1) * CKS);
                #pragma unroll
                for (int qq = 0; qq < 4; ++qq) {
                    const int u = tid + qq * 256;
                    const int row = u >> 3, seg = u & 7;
                    st[qq] = *(const uint4*)(srch + (size_t)(b0 + row) * F_DIM
                                             + (c + 1) * KC + seg * 8);
                }
                if (c + 2 < NCH) pv = ld_acq(ckbase + (c + 2) * CKS);  // speculative
            }
            __syncthreads();

            const u32 a_base = sbase + ABUF(p) + a_off0;
            #pragma unroll
            for (int ks = 0; ks < 4; ++ks) {
                u32 A0[4], A1[4];
                ldsm_x4(A0[0], A0[1], A0[2], A0[3], a_base + ks * 32);
                ldsm_x4(A1[0], A1[1], A1[2], A1[3], a_base + ks * 32 + 16 * AST * 2);
                const u32 koff = (u32)(c * KC + ks * 16) * 2;
                #pragma unroll
                for (int ntp = 0; ntp < 2; ++ntp) {
                    const u32 noff = (u32)(ntp * 16) * BST * 2;
                    u32 bh0, bh1, bh2, bh3;
                    ldsm_x4(bh0, bh1, bh2, bh3, bhi_base + noff + koff);
                    mma16816h(acc[0][2*ntp],   A0, bh0, bh1);
                    mma16816h(acc[0][2*ntp+1], A0, bh2, bh3);
                    mma16816h(acc[1][2*ntp],   A1, bh0, bh1);
                    mma16816h(acc[1][2*ntp+1], A1, bh2, bh3);
                }
            }
        }

        // ---- Epilogue: gates in lane pairs; one shfl.xor(1) joins them ----
        #pragma unroll
        for (int mt = 0; mt < 2; ++mt) {
            #pragma unroll
            for (int nt = 0; nt < 4; ++nt) {
                const int floc = 8 * wn + 2 * nt + (tg >> 1);
                const float wg_ = swx[4*floc + 0], wi_ = swx[4*floc + 1];
                const float wf_ = swx[4*floc + 2], wo_ = swx[4*floc + 3];
                #pragma unroll
                for (int rh = 0; rh < 2; ++rh) {
                    const float m0 = acc[mt][nt][rh*2 + 0];
                    const float m1 = acc[mt][nt][rh*2 + 1];
                    const float o0 = __shfl_xor_sync(0xffffffffu, m0, 1);
                    const float o1 = __shfl_xor_sync(0xffffffffu, m1, 1);
                    const float vg = (tg & 1) ? o0 : m0;
                    const float vi = (tg & 1) ? o1 : m1;
                    const float vf = (tg & 1) ? m0 : o0;
                    const float vo = (tg & 1) ? m1 : o1;
                    const int row = wm * 32 + mt * 16 + q + 8 * rh;
                    const float xv = sx[row];
                    const float pg = vg + wg_ * xv + sbg[row];
                    const float pi = vi + wi_ * xv + sbi[row];
                    const float pf = vf + wf_ * xv + sbf[row];
                    const float po = vo + wo_ * xv + sbo[row];
                    const float gg = tanh_fast(pg);
                    const float si = sigm(pi);
                    const float sf = sigm(pf);
                    const float so = sigm(po);
                    const int ci = (mt * 2 + rh) * 4 + nt;
                    const float cn = gg * si + cst[ci] * sf;
                    cst[ci] = cn;
                    const float hv = tanh_fast(cn) * so;
                    if (!(tg & 1)) {
                        g_h[dstp][(size_t)(b0 + row) * F_DIM + F0 + floc] = __float2half(hv);
                    }
                }
            }
        }
        // Producer arrive: all h stores of this CTA done -> release-increment
        __syncthreads();
        if (tid == 0) {
            unsigned old;
            asm volatile("atom.release.gpu.global.add.u32 %0, [%1], %2;"
                         : "=r"(old) : "l"(my_ck), "r"(1u) : "memory");
        }
    }

    // ---- Teardown: group barrier, reset chunk counters (replay safety) ----
    gsync_grp(&s_sense, btile);
    if (ftile == 0 && tid < 8) {
        asm volatile("st.relaxed.gpu.global.u32 [%0], %1;"
                     :: "l"(ckbase + tid * CKS), "r"(0u) : "memory");
    }

    // ---- Projection: out[b][c] = sum_f h[b][f] * w_ph[f][c] + b_p[c] ----
    {
        const int c2 = (tid & 63) * 2;
        const int brow = bid * 4 + (tid >> 6);
        const __half* __restrict__ hh = g_h[0] + (size_t)brow * F_DIM;
        float a0 = 0.0f, a1 = 0.0f;
        #pragma unroll 4
        for (int f = 0; f < F_DIM; ++f) {
            const float hf = __half2float(hh[f]);
            a0 += hf * w_ph[f * C_DIM + c2];
            a1 += hf * w_ph[f * C_DIM + c2 + 1];
        }
        out[brow * C_DIM + c2]     = a0 + b_p[c2];
        out[brow * C_DIM + c2 + 1] = a1 + b_p[c2 + 1];
    }
}

extern "C" void kernel_launch(void* const* d_in, const int* in_sizes, int n_in,
                              void* d_out, int out_size)
{
    (void)in_sizes; (void)n_in; (void)out_size;
    const float* x    = (const float*)d_in[0];
    const float* w_gx = (const float*)d_in[1];
    const float* w_gh = (const float*)d_in[2];
    const float* w_ix = (const float*)d_in[3];
    const float* w_ih = (const float*)d_in[4];
    const float* w_fx = (const float*)d_in[5];
    const float* w_fh = (const float*)d_in[6];
    const float* w_ox = (const float*)d_in[7];
    const float* w_oh = (const float*)d_in[8];
    const float* w_ph = (const float*)d_in[9];
    const float* b_g  = (const float*)d_in[10];
    const float* b_i  = (const float*)d_in[11];
    const float* b_f  = (const float*)d_in[12];
    const float* b_o  = (const float*)d_in[13];
    const float* b_p  = (const float*)d_in[14];
    float* out = (float*)d_out;

    cudaFuncSetAttribute(lstm_hmma_kernel,
                         cudaFuncAttributeMaxDynamicSharedMemorySize, SMEM_TOTAL);

    lstm_hmma_kernel<<<GRID_BLOCKS, THREADS, SMEM_TOTAL>>>(
        x, w_gx, w_gh, w_ix, w_ih, w_fx, w_fh, w_ox, w_oh, w_ph,
        b_g, b_i, b_f, b_o, b_p, out);
}

// round 14
// speedup vs baseline: 3.8817x; 1.3655x over previous
#include <cuda_runtime.h>
#include <cuda_fp16.h>
#include <math.h>

typedef unsigned int u32;

#define F_DIM 512
#define B_DIM 512
#define L_DIM 256
#define C_DIM 128

#define GRID_BLOCKS 128
#define THREADS 512
#define FT    16      // features per CTA
#define NGATE 64      // gate cols per CTA (MMA N)
#define BT    128     // batch rows per CTA (MMA M)
#define KC    128     // k-chunk
#define NCH   4       // chunks per step

#define BST 520       // B row stride fp16 (1040B = 260 words ≡ 4 mod 32: conflict-free)
#define AST 136       // A row stride fp16 (272B = 68 words ≡ 4 mod 32: conflict-free)

// SMEM byte offsets
#define B_PLANE_BYTES (NGATE * BST * 2)          // 66560 (65*1024)
#define BHI_OFF 0
#define A_PLANE_BYTES (BT * AST * 2)             // 34816
#define A_OFF   B_PLANE_BYTES
#define ABUF(p) (A_OFF + (p) * A_PLANE_BYTES)
#define SX_OFF   (A_OFF + 2 * A_PLANE_BYTES)     // 136192 (128 floats)
#define SWX_OFF  (SX_OFF + 512)
#define SB_OFF   (SWX_OFF + 256)
#define SMEM_TOTAL (SB_OFF + 2048 + 64)          // ~139 KB

// Persistent device state: h as single fp16 plane [batch][feat]
__device__ __half g_h[2][B_DIM * F_DIM];
#define GRP_STRIDE 32
__device__ unsigned g_cnt[4 * GRP_STRIDE];
__device__ unsigned g_sense[4 * GRP_STRIDE];
// Per-chunk monotonic counters: chunk c of group produced by 8 CTAs (ftiles 8c..8c+7)
#define CKS 32
__device__ unsigned g_ck[4 * NCH * CKS];

__device__ __forceinline__ u32 smem_u32(const void* p) {
    u32 a; asm("{ .reg .u64 t; cvta.to.shared.u64 t, %1; cvt.u32.u64 %0, t; }" : "=r"(a) : "l"(p));
    return a;
}
__device__ __forceinline__ void ldsm_x4(u32& r0, u32& r1, u32& r2, u32& r3, u32 addr) {
    asm volatile("ldmatrix.sync.aligned.m8n8.x4.shared.b16 {%0,%1,%2,%3}, [%4];"
                 : "=r"(r0), "=r"(r1), "=r"(r2), "=r"(r3) : "r"(addr));
}
__device__ __forceinline__ void mma16816h(float* c, const u32* a, u32 b0, u32 b1) {
    asm volatile("mma.sync.aligned.m16n8k16.row.col.f32.f16.f16.f32 "
                 "{%0,%1,%2,%3}, {%4,%5,%6,%7}, {%8,%9}, {%0,%1,%2,%3};"
                 : "+f"(c[0]), "+f"(c[1]), "+f"(c[2]), "+f"(c[3])
                 : "r"(a[0]), "r"(a[1]), "r"(a[2]), "r"(a[3]), "r"(b0), "r"(b1));
}
__device__ __forceinline__ u32 ld_acq(const unsigned* p) {
    u32 v; asm volatile("ld.acquire.gpu.global.u32 %0, [%1];" : "=r"(v) : "l"(p) : "memory");
    return v;
}

__device__ __forceinline__ float sigm(float x) {
    const float e = exp2f(-1.4426950408889634f * x);
    return 1.0f / (1.0f + e);
}
__device__ __forceinline__ float tanh_fast(float x) {
    float r; asm("tanh.approx.f32 %0, %1;" : "=f"(r) : "f"(x)); return r;
}

// Full group barrier (32 CTAs of one btile) - init/teardown only.
__device__ __forceinline__ void gsync_grp(unsigned* s_sense, int grp) {
    __syncthreads();
    if (threadIdx.x == 0) {
        unsigned ns = *s_sense ^ 1u;
        *s_sense = ns;
        unsigned* cnt = &g_cnt[grp * GRP_STRIDE];
        unsigned* sen = &g_sense[grp * GRP_STRIDE];
        unsigned old;
        asm volatile("atom.release.gpu.global.add.u32 %0, [%1], %2;"
                     : "=r"(old) : "l"(cnt), "r"(1u) : "memory");
        if (old == 31u) {
            asm volatile("st.relaxed.gpu.global.u32 [%0], %1;" :: "l"(cnt), "r"(0u) : "memory");
            asm volatile("st.release.gpu.global.u32 [%0], %1;" :: "l"(sen), "r"(ns) : "memory");
        } else {
            unsigned v;
            do {
                asm volatile("ld.acquire.gpu.global.u32 %0, [%1];" : "=r"(v) : "l"(sen) : "memory");
            } while (v != ns);
        }
    }
    __syncthreads();
}

__global__ void __launch_bounds__(THREADS, 1)
lstm_hmma_kernel(const float* __restrict__ x,
                 const float* __restrict__ w_gx, const float* __restrict__ w_gh,
                 const float* __restrict__ w_ix, const float* __restrict__ w_ih,
                 const float* __restrict__ w_fx, const float* __restrict__ w_fh,
                 const float* __restrict__ w_ox, const float* __restrict__ w_oh,
                 const float* __restrict__ w_ph,
                 const float* __restrict__ b_g, const float* __restrict__ b_i,
                 const float* __restrict__ b_f, const float* __restrict__ b_o,
                 const float* __restrict__ b_p,
                 float* __restrict__ out)
{
    extern __shared__ char smc[];
    const u32 sbase = smem_u32(smc);
    float* sx  = (float*)(smc + SX_OFF);
    float* swx = (float*)(smc + SWX_OFF);
    float* sbg = (float*)(smc + SB_OFF);
    float* sbi = sbg + 128;
    float* sbf = sbi + 128;
    float* sbo = sbf + 128;

    const int tid   = threadIdx.x;
    const int bid   = blockIdx.x;
    const int ftile = bid & 31;
    const int btile = bid >> 5;
    const int F0    = ftile * FT;
    const int b0    = btile * BT;
    const int wid   = tid >> 5;
    const int lid   = tid & 31;
    const int wm    = wid >> 1;           // 0..7: batch rows wm*16..+15
    const int wn    = wid & 1;            // 0..1: gates wn*32..+31 (features 8wn..+7)
    const int tg    = lid & 3;
    const int q     = lid >> 2;
    const int pl    = tg & 1;             // row-half owned by this lane (rh split)
    const int mychunk = ftile >> 3;       // chunk this CTA's features belong to

    __shared__ unsigned s_sense;
    if (tid == 0) s_sense = g_sense[btile * GRP_STRIDE];

    unsigned* ckbase = &g_ck[(btile * NCH) * CKS];
    unsigned* my_ck  = &g_ck[(btile * NCH + mychunk) * CKS];

    // ---- W resident in SMEM: single fp16 plane; B[n][k], n = 4*flocal+gate ----
    {
        const float* Wh[4] = {w_gh, w_ih, w_fh, w_oh};
        #pragma unroll 1
        for (int idx = tid; idx < NGATE * F_DIM; idx += THREADS) {
            const int n = idx >> 9;
            const int k = idx & 511;
            const int fl = n >> 2, gt = n & 3;
            const float v = Wh[gt][(F0 + fl) * F_DIM + k];
            *(__half*)(smc + BHI_OFF + ((u32)n * BST + (u32)k) * 2) = __float2half(v);
        }
        if (tid < 64) {
            const int fl = tid >> 2, gt = tid & 3;
            const float* Wx[4] = {w_gx, w_ix, w_fx, w_ox};
            swx[tid] = Wx[gt][F0 + fl];
        }
        // Reference quirk: gate biases broadcast along trailing (batch) axis.
        if (tid < 128) {
            sbg[tid] = b_g[b0 + tid];
            sbi[tid] = b_i[b0 + tid];
            sbf[tid] = b_f[b0 + tid];
            sbo[tid] = b_o[b0 + tid];
        }
    }

    // ---- Zero h plane 0: 65536 threads x uint2 covers the 512KB plane ----
    {
        const int gidx = bid * THREADS + tid;
        ((uint2*)g_h[0])[gidx] = make_uint2(0u, 0u);
    }
    gsync_grp(&s_sense, btile);

    // ---- ldmatrix per-thread byte offsets ----
    // A m16k16 tiles: rows wm*16 + (lid&7) + 8*((lid>>3)&1), col-half 8*(lid>>4)
    const u32 a_off0 = (((u32)(wm * 16 + (lid & 7) + 8 * ((lid >> 3) & 1))) * AST
                       + 8u * (u32)(lid >> 4)) * 2u;
    // B n16k16 tiles: rows wn*32 + ntp*16 + (lid&7) + 8*(lid>>4), col 8*((lid>>3)&1)
    const u32 b_off0 = (((u32)(wn * 32 + (lid & 7) + 8 * (lid >> 4))) * BST
                       + 8u * (u32)((lid >> 3) & 1)) * 2u;
    const u32 bhi_base = sbase + BHI_OFF + b_off0;

    float cst[4];                       // c state: this lane's rh only, [nt]
    #pragma unroll
    for (int i = 0; i < 4; ++i) cst[i] = 0.0f;

    for (int t = 0; t < L_DIM; ++t) {
        const __half* __restrict__ srch = g_h[t & 1];
        const int dstp = (t & 1) ^ 1;
        const u32 thr = 8u * (u32)t;    // 8 producer CTAs per chunk

        if (tid < BT) sx[tid] = x[(size_t)(b0 + tid) * L_DIM + t];

        float acc[4][4];                // [nt][frag]; M16 x N32
        #pragma unroll
        for (int nt = 0; nt < 4; ++nt)
            #pragma unroll
            for (int j = 0; j < 4; ++j) acc[nt][j] = 0.0f;

        // hard wait for chunk 0 producers, then prefetch chunk 0 (32KB: 4 uint4/thread)
        while (ld_acq(ckbase + 0 * CKS) < thr) {}
        uint4 st[4];
        #pragma unroll
        for (int qq = 0; qq < 4; ++qq) {
            const int u = tid + qq * 512;
            const int row = u >> 4, seg = u & 15;
            st[qq] = *(const uint4*)(srch + (size_t)(b0 + row) * F_DIM + seg * 8);
        }
        u32 pv = ld_acq(ckbase + 1 * CKS);   // speculative poll for chunk 1

        for (int c = 0; c < NCH; ++c) {
            const int p = c & 1;
            #pragma unroll
            for (int qq = 0; qq < 4; ++qq) {
                const int u = tid + qq * 512;
                const u32 so = ((u32)(u >> 4) * AST + (u32)(u & 15) * 8u) * 2u;
                *(uint4*)(smc + ABUF(p) + so) = st[qq];
            }
            if (c < NCH - 1) {
                while (pv < thr) pv = ld_acq(ckbase + (c + 1) * CKS);
                #pragma unroll
                for (int qq = 0; qq < 4; ++qq) {
                    const int u = tid + qq * 512;
                    const int row = u >> 4, seg = u & 15;
                    st[qq] = *(const uint4*)(srch + (size_t)(b0 + row) * F_DIM
                                             + (c + 1) * KC + seg * 8);
                }
                if (c + 2 < NCH) pv = ld_acq(ckbase + (c + 2) * CKS);
            }
            __syncthreads();

            const u32 a_base = sbase + ABUF(p) + a_off0;
            #pragma unroll
            for (int ks = 0; ks < 8; ++ks) {
                u32 A0[4];
                ldsm_x4(A0[0], A0[1], A0[2], A0[3], a_base + ks * 32);
                const u32 koff = (u32)(c * KC + ks * 16) * 2;
                #pragma unroll
                for (int ntp = 0; ntp < 2; ++ntp) {
                    const u32 noff = (u32)(ntp * 16) * BST * 2;
                    u32 bh0, bh1, bh2, bh3;
                    ldsm_x4(bh0, bh1, bh2, bh3, bhi_base + noff + koff);
                    mma16816h(acc[2*ntp],   A0, bh0, bh1);
                    mma16816h(acc[2*ntp+1], A0, bh2, bh3);
                }
            }
        }

        // ---- Epilogue, rh-split across lane pairs (no duplicated MUFU) ----
        // For my rh (=pl): need even-lane cols (g,i) and odd-lane cols (f,o)
        // of acc[..][pl*2], acc[..][pl*2+1]. Exchange the unused halves.
        const int row = wm * 16 + q + 8 * pl;
        const float xv = sx[row];
        const float bg_ = sbg[row], bi_ = sbi[row], bf_ = sbf[row], bo_ = sbo[row];
        #pragma unroll
        for (int nt = 0; nt < 4; ++nt) {
            const int floc = 8 * wn + 2 * nt + (tg >> 1);
            const float send0 = pl ? acc[nt][0] : acc[nt][2];
            const float send1 = pl ? acc[nt][1] : acc[nt][3];
            const float mine0 = pl ? acc[nt][2] : acc[nt][0];
            const float mine1 = pl ? acc[nt][3] : acc[nt][1];
            const float recv0 = __shfl_xor_sync(0xffffffffu, send0, 1);
            const float recv1 = __shfl_xor_sync(0xffffffffu, send1, 1);
            const float vg = pl ? recv0 : mine0;
            const float vi = pl ? recv1 : mine1;
            const float vf = pl ? mine0 : recv0;
            const float vo = pl ? mine1 : recv1;
            const float wg_ = swx[4*floc + 0], wi_ = swx[4*floc + 1];
            const float wf_ = swx[4*floc + 2], wo_ = swx[4*floc + 3];
            const float pg = vg + wg_ * xv + bg_;
            const float pi = vi + wi_ * xv + bi_;
            const float pf = vf + wf_ * xv + bf_;
            const float po = vo + wo_ * xv + bo_;
            const float gg = tanh_fast(pg);
            const float si = sigm(pi);
            const float sf = sigm(pf);
            const float so = sigm(po);
            const float cn = gg * si + cst[nt] * sf;
            cst[nt] = cn;
            const float hv = tanh_fast(cn) * so;
            g_h[dstp][(size_t)(b0 + row) * F_DIM + F0 + floc] = __float2half(hv);
        }
        // Producer arrive: all h stores of this CTA done -> release-increment
        __syncthreads();
        if (tid == 0) {
            unsigned old;
            asm volatile("atom.release.gpu.global.add.u32 %0, [%1], %2;"
                         : "=r"(old) : "l"(my_ck), "r"(1u) : "memory");
        }
    }

    // ---- Teardown: group barrier, reset chunk counters (replay safety) ----
    gsync_grp(&s_sense, btile);
    if (ftile == 0 && tid < NCH) {
        asm volatile("st.relaxed.gpu.global.u32 [%0], %1;"
                     :: "l"(ckbase + tid * CKS), "r"(0u) : "memory");
    }

    // ---- Projection: out[b][c] = sum_f h[b][f] * w_ph[f][c] + b_p[c] ----
    {
        const int cc = tid & 127;
        const int brow = bid * 4 + (tid >> 7);
        const __half* __restrict__ hh = g_h[0] + (size_t)brow * F_DIM;
        float a0 = 0.0f;
        #pragma unroll 4
        for (int f = 0; f < F_DIM; ++f) {
            a0 += __half2float(hh[f]) * w_ph[f * C_DIM + cc];
        }
        out[brow * C_DIM + cc] = a0 + b_p[cc];
    }
}

extern "C" void kernel_launch(void* const* d_in, const int* in_sizes, int n_in,
                              void* d_out, int out_size)
{
    (void)in_sizes; (void)n_in; (void)out_size;
    const float* x    = (const float*)d_in[0];
    const float* w_gx = (const float*)d_in[1];
    const float* w_gh = (const float*)d_in[2];
    const float* w_ix = (const float*)d_in[3];
    const float* w_ih = (const float*)d_in[4];
    const float* w_fx = (const float*)d_in[5];
    const float* w_fh = (const float*)d_in[6];
    const float* w_ox = (const float*)d_in[7];
    const float* w_oh = (const float*)d_in[8];
    const float* w_ph = (const float*)d_in[9];
    const float* b_g  = (const float*)d_in[10];
    const float* b_i  = (const float*)d_in[11];
    const float* b_f  = (const float*)d_in[12];
    const float* b_o  = (const float*)d_in[13];
    const float* b_p  = (const float*)d_in[14];
    float* out = (float*)d_out;

    cudaFuncSetAttribute(lstm_hmma_kernel,
                         cudaFuncAttributeMaxDynamicSharedMemorySize, SMEM_TOTAL);

    lstm_hmma_kernel<<<GRID_BLOCKS, THREADS, SMEM_TOTAL>>>(
        x, w_gx, w_gh, w_ix, w_ih, w_fx, w_fh, w_ox, w_oh, w_ph,
        b_g, b_i, b_f, b_o, b_p, out);
}

// round 15
// speedup vs baseline: 4.0073x; 1.0324x over previous
#include <cuda_runtime.h>
#include <cuda_fp16.h>
#include <math.h>

typedef unsigned int u32;

#define F_DIM 512
#define B_DIM 512
#define L_DIM 256
#define C_DIM 128

#define GRID_BLOCKS 128
#define THREADS 512
#define FT    16      // features per CTA
#define NGATE 64      // gate cols per CTA (MMA N)
#define BT    128     // batch rows per CTA (MMA M)
#define KC    128     // k-chunk
#define NCH   4       // chunks per step

#define BST 520       // B row stride fp16 (conflict-free ldmatrix)
#define AST 136       // A row stride fp16 (conflict-free ldmatrix)

// SMEM byte offsets
#define B_PLANE_BYTES (NGATE * BST * 2)          // 66560
#define BHI_OFF 0
#define A_PLANE_BYTES (BT * AST * 2)             // 34816
#define A_OFF   B_PLANE_BYTES
#define ABUF3(i) (A_OFF + (i) * A_PLANE_BYTES)   // 3 buffers
#define SCR_OFF  (A_OFF + 3 * A_PLANE_BYTES)     // 171008, 32KB scratch
#define SX_OFF   (SCR_OFF + 32768)               // 203776
#define SWX_OFF  (SX_OFF + 512)
#define SB_OFF   (SWX_OFF + 256)
#define SMEM_TOTAL (SB_OFF + 2048 + 64)          // ~202 KB

// Persistent device state: h as single fp16 plane [batch][feat]
__device__ __half g_h[2][B_DIM * F_DIM];
#define GRP_STRIDE 32
__device__ unsigned g_cnt[4 * GRP_STRIDE];
__device__ unsigned g_sense[4 * GRP_STRIDE];
#define CKS 32
__device__ unsigned g_ck[4 * NCH * CKS];

__device__ __forceinline__ u32 smem_u32(const void* p) {
    u32 a; asm("{ .reg .u64 t; cvta.to.shared.u64 t, %1; cvt.u32.u64 %0, t; }" : "=r"(a) : "l"(p));
    return a;
}
__device__ __forceinline__ void ldsm_x4(u32& r0, u32& r1, u32& r2, u32& r3, u32 addr) {
    asm volatile("ldmatrix.sync.aligned.m8n8.x4.shared.b16 {%0,%1,%2,%3}, [%4];"
                 : "=r"(r0), "=r"(r1), "=r"(r2), "=r"(r3) : "r"(addr));
}
__device__ __forceinline__ void mma16816h(float* c, const u32* a, u32 b0, u32 b1) {
    asm volatile("mma.sync.aligned.m16n8k16.row.col.f32.f16.f16.f32 "
                 "{%0,%1,%2,%3}, {%4,%5,%6,%7}, {%8,%9}, {%0,%1,%2,%3};"
                 : "+f"(c[0]), "+f"(c[1]), "+f"(c[2]), "+f"(c[3])
                 : "r"(a[0]), "r"(a[1]), "r"(a[2]), "r"(a[3]), "r"(b0), "r"(b1));
}
__device__ __forceinline__ u32 ld_acq(const unsigned* p) {
    u32 v; asm volatile("ld.acquire.gpu.global.u32 %0, [%1];" : "=r"(v) : "l"(p) : "memory");
    return v;
}
__device__ __forceinline__ void cpasync16(u32 dst, const void* src) {
    asm volatile("cp.async.cg.shared.global [%0], [%1], 16;" :: "r"(dst), "l"(src) : "memory");
}
__device__ __forceinline__ void cp_commit() {
    asm volatile("cp.async.commit_group;" ::: "memory");
}
__device__ __forceinline__ void cp_wait0() {
    asm volatile("cp.async.wait_group 0;" ::: "memory");
}

__device__ __forceinline__ float sigm(float x) {
    const float e = exp2f(-1.4426950408889634f * x);
    return 1.0f / (1.0f + e);
}
__device__ __forceinline__ float tanh_fast(float x) {
    float r; asm("tanh.approx.f32 %0, %1;" : "=f"(r) : "f"(x)); return r;
}

// Full group barrier (32 CTAs of one btile) - init/teardown only.
__device__ __forceinline__ void gsync_grp(unsigned* s_sense, int grp) {
    __syncthreads();
    if (threadIdx.x == 0) {
        unsigned ns = *s_sense ^ 1u;
        *s_sense = ns;
        unsigned* cnt = &g_cnt[grp * GRP_STRIDE];
        unsigned* sen = &g_sense[grp * GRP_STRIDE];
        unsigned old;
        asm volatile("atom.release.gpu.global.add.u32 %0, [%1], %2;"
                     : "=r"(old) : "l"(cnt), "r"(1u) : "memory");
        if (old == 31u) {
            asm volatile("st.relaxed.gpu.global.u32 [%0], %1;" :: "l"(cnt), "r"(0u) : "memory");
            asm volatile("st.release.gpu.global.u32 [%0], %1;" :: "l"(sen), "r"(ns) : "memory");
        } else {
            unsigned v;
            do {
                asm volatile("ld.acquire.gpu.global.u32 %0, [%1];" : "=r"(v) : "l"(sen) : "memory");
            } while (v != ns);
        }
    }
    __syncthreads();
}

__global__ void __launch_bounds__(THREADS, 1)
lstm_hmma_kernel(const float* __restrict__ x,
                 const float* __restrict__ w_gx, const float* __restrict__ w_gh,
                 const float* __restrict__ w_ix, const float* __restrict__ w_ih,
                 const float* __restrict__ w_fx, const float* __restrict__ w_fh,
                 const float* __restrict__ w_ox, const float* __restrict__ w_oh,
                 const float* __restrict__ w_ph,
                 const float* __restrict__ b_g, const float* __restrict__ b_i,
                 const float* __restrict__ b_f, const float* __restrict__ b_o,
                 const float* __restrict__ b_p,
                 float* __restrict__ out)
{
    extern __shared__ char smc[];
    const u32 sbase = smem_u32(smc);
    float*  sx  = (float*)(smc + SX_OFF);
    float*  swx = (float*)(smc + SWX_OFF);
    float*  sbg = (float*)(smc + SB_OFF);
    float*  sbi = sbg + 128;
    float*  sbf = sbi + 128;
    float*  sbo = sbf + 128;
    float4* scr = (float4*)(smc + SCR_OFF);

    const int tid   = threadIdx.x;
    const int bid   = blockIdx.x;
    const int ftile = bid & 31;
    const int btile = bid >> 5;
    const int F0    = ftile * FT;
    const int b0    = btile * BT;
    const int wid   = tid >> 5;
    const int lid   = tid & 31;
    const int wm    = wid >> 2;           // 0..3: batch rows wm*32..+31
    const int wn    = (wid >> 1) & 1;     // 0..1: gates wn*32..+31 (features 8wn..+7)
    const int kh    = wid & 1;            // 0..1: k-half within each chunk
    const int tg    = lid & 3;
    const int q     = lid >> 2;
    const int pl    = tg & 1;             // row-half owned by this lane
    const int mychunk = ftile >> 3;

    __shared__ unsigned s_sense;
    if (tid == 0) s_sense = g_sense[btile * GRP_STRIDE];

    unsigned* ckbase = &g_ck[(btile * NCH) * CKS];
    unsigned* my_ck  = &g_ck[(btile * NCH + mychunk) * CKS];

    // ---- W resident in SMEM: fp16; B[n][k], n = 4*flocal+gate ----
    {
        const float* Wh[4] = {w_gh, w_ih, w_fh, w_oh};
        #pragma unroll 1
        for (int idx = tid; idx < NGATE * F_DIM; idx += THREADS) {
            const int n = idx >> 9;
            const int k = idx & 511;
            const int fl = n >> 2, gt = n & 3;
            const float v = Wh[gt][(F0 + fl) * F_DIM + k];
            *(__half*)(smc + BHI_OFF + ((u32)n * BST + (u32)k) * 2) = __float2half(v);
        }
        if (tid < 64) {
            const int fl = tid >> 2, gt = tid & 3;
            const float* Wx[4] = {w_gx, w_ix, w_fx, w_ox};
            swx[tid] = Wx[gt][F0 + fl];
        }
        // Reference quirk: gate biases broadcast along trailing (batch) axis.
        if (tid < 128) {
            sbg[tid] = b_g[b0 + tid];
            sbi[tid] = b_i[b0 + tid];
            sbf[tid] = b_f[b0 + tid];
            sbo[tid] = b_o[b0 + tid];
        }
    }

    // ---- Zero h plane 0 ----
    {
        const int gidx = bid * THREADS + tid;
        ((uint2*)g_h[0])[gidx] = make_uint2(0u, 0u);
    }
    gsync_grp(&s_sense, btile);

    // ---- ldmatrix per-thread byte offsets ----
    // A m16k16 tile (mt adds 16 rows): rows wm*32+(lid&7)+8*((lid>>3)&1), col kh*64+8*(lid>>4)
    const u32 a_off0 = (((u32)(wm * 32 + (lid & 7) + 8 * ((lid >> 3) & 1))) * AST
                       + (u32)(kh * 64) + 8u * (u32)(lid >> 4)) * 2u;
    // B n16k16: rows wn*32+ntp*16+(lid&7)+8*(lid>>4), col 8*((lid>>3)&1)
    const u32 b_off0 = (((u32)(wn * 32 + (lid & 7) + 8 * (lid >> 4))) * BST
                       + 8u * (u32)((lid >> 3) & 1)) * 2u;
    const u32 bhi_base = sbase + BHI_OFF + b_off0;

    float cst[4];
    #pragma unroll
    for (int i = 0; i < 4; ++i) cst[i] = 0.0f;

    // ---- stage chunk0 of step 0 (plane 0 zeroed & group-synced) ----
    {
        #pragma unroll
        for (int qq = 0; qq < 4; ++qq) {
            const int u = tid + qq * 512;
            const int row = u >> 4, seg = u & 15;
            cpasync16(sbase + ABUF3(0) + ((u32)row * AST + (u32)seg * 8u) * 2u,
                      g_h[0] + (size_t)(b0 + row) * F_DIM + seg * 8);
        }
        cp_commit();
    }
    int mbuf = 0, ibuf = 1;

    for (int t = 0; t < L_DIM; ++t) {
        const __half* __restrict__ srch = g_h[t & 1];
        const int dstp = (t & 1) ^ 1;
        const u32 thr = 8u * (u32)t;

        if (tid < BT) sx[tid] = x[(size_t)(b0 + tid) * L_DIM + t];

        float acc[2][4][4];            // [mt][nt][frag]
        #pragma unroll
        for (int mt = 0; mt < 2; ++mt)
            #pragma unroll
            for (int nt = 0; nt < 4; ++nt)
                #pragma unroll
                for (int j = 0; j < 4; ++j) acc[mt][nt][j] = 0.0f;

        u32 pv = ld_acq(ckbase + 1 * CKS);     // speculative poll chunk1

        for (int c = 0; c < NCH; ++c) {
            cp_wait0();                // my chunk-c slices arrived
            __syncthreads();           // everyone's waits done + all MMA c-1 done

            if (c < NCH - 1) {
                while (pv < thr) pv = ld_acq(ckbase + (c + 1) * CKS);
                #pragma unroll
                for (int qq = 0; qq < 4; ++qq) {
                    const int u = tid + qq * 512;
                    const int row = u >> 4, seg = u & 15;
                    cpasync16(sbase + ABUF3(ibuf) + ((u32)row * AST + (u32)seg * 8u) * 2u,
                              srch + (size_t)(b0 + row) * F_DIM + (c + 1) * KC + seg * 8);
                }
                cp_commit();
                ibuf = (ibuf == 2) ? 0 : ibuf + 1;
                if (c + 2 < NCH) pv = ld_acq(ckbase + (c + 2) * CKS);
            }

            const u32 a_base = sbase + ABUF3(mbuf) + a_off0;
            #pragma unroll
            for (int ks = 0; ks < 4; ++ks) {
                u32 A0[4], A1[4];
                ldsm_x4(A0[0], A0[1], A0[2], A0[3], a_base + ks * 32);
                ldsm_x4(A1[0], A1[1], A1[2], A1[3], a_base + ks * 32 + 16 * AST * 2);
                const u32 koff = (u32)(c * KC + kh * 64 + ks * 16) * 2;
                #pragma unroll
                for (int ntp = 0; ntp < 2; ++ntp) {
                    const u32 noff = (u32)(ntp * 16) * BST * 2;
                    u32 bh0, bh1, bh2, bh3;
                    ldsm_x4(bh0, bh1, bh2, bh3, bhi_base + noff + koff);
                    mma16816h(acc[0][2*ntp],   A0, bh0, bh1);
                    mma16816h(acc[0][2*ntp+1], A0, bh2, bh3);
                    mma16816h(acc[1][2*ntp],   A1, bh0, bh1);
                    mma16816h(acc[1][2*ntp+1], A1, bh2, bh3);
                }
            }
            mbuf = (mbuf == 2) ? 0 : mbuf + 1;
        }

        // ---- kh reduction: keep mt=kh, exchange mt=1-kh via scratch ----
        {
            float snd[16];
            #pragma unroll
            for (int i = 0; i < 16; ++i)
                snd[i] = kh ? acc[0][i >> 2][i & 3] : acc[1][i >> 2][i & 3];
            #pragma unroll
            for (int j = 0; j < 4; ++j)
                scr[j * 512 + tid] = make_float4(snd[4*j], snd[4*j+1], snd[4*j+2], snd[4*j+3]);
            __syncthreads();
            const int ptid = tid ^ 32;     // partner warp (kh flipped)
            #pragma unroll
            for (int j = 0; j < 4; ++j) {
                const float4 v = scr[j * 512 + ptid];
                const int nt = j;
                acc[0][nt][0] = (kh ? acc[1][nt][0] : acc[0][nt][0]) + v.x;
                acc[0][nt][1] = (kh ? acc[1][nt][1] : acc[0][nt][1]) + v.y;
                acc[0][nt][2] = (kh ? acc[1][nt][2] : acc[0][nt][2]) + v.z;
                acc[0][nt][3] = (kh ? acc[1][nt][3] : acc[0][nt][3]) + v.w;
            }
        }

        // ---- Epilogue (this warp's mt = kh), rh-split across lane pairs ----
        const int row = wm * 32 + kh * 16 + q + 8 * pl;
        const float xv = sx[row];
        const float bg_ = sbg[row], bi_ = sbi[row], bf_ = sbf[row], bo_ = sbo[row];
        #pragma unroll
        for (int nt = 0; nt < 4; ++nt) {
            const int floc = 8 * wn + 2 * nt + (tg >> 1);
            const float send0 = pl ? acc[0][nt][0] : acc[0][nt][2];
            const float send1 = pl ? acc[0][nt][1] : acc[0][nt][3];
            const float mine0 = pl ? acc[0][nt][2] : acc[0][nt][0];
            const float mine1 = pl ? acc[0][nt][3] : acc[0][nt][1];
            const float recv0 = __shfl_xor_sync(0xffffffffu, send0, 1);
            const float recv1 = __shfl_xor_sync(0xffffffffu, send1, 1);
            const float vg = pl ? recv0 : mine0;
            const float vi = pl ? recv1 : mine1;
            const float vf = pl ? mine0 : recv0;
            const float vo = pl ? mine1 : recv1;
            const float wg_ = swx[4*floc + 0], wi_ = swx[4*floc + 1];
            const float wf_ = swx[4*floc + 2], wo_ = swx[4*floc + 3];
            const float pg = vg + wg_ * xv + bg_;
            const float pi = vi + wi_ * xv + bi_;
            const float pf = vf + wf_ * xv + bf_;
            const float po = vo + wo_ * xv + bo_;
            const float gg = tanh_fast(pg);
            const float si = sigm(pi);
            const float sf = sigm(pf);
            const float so = sigm(po);
            const float cn = gg * si + cst[nt] * sf;
            cst[nt] = cn;
            const float hv = tanh_fast(cn) * so;
            g_h[dstp][(size_t)(b0 + row) * F_DIM + F0 + floc] = __float2half(hv);
        }

        __syncthreads();
        if (tid == 0) {
            unsigned old;
            asm volatile("atom.release.gpu.global.add.u32 %0, [%1], %2;"
                         : "=r"(old) : "l"(my_ck), "r"(1u) : "memory");
        }

        // ---- stage next step's chunk0 (overlaps other CTAs' tails) ----
        if (t + 1 < L_DIM) {
            const u32 thrn = 8u * (u32)(t + 1);
            while (ld_acq(ckbase + 0 * CKS) < thrn) {}
            const __half* __restrict__ nsrc = g_h[dstp];
            #pragma unroll
            for (int qq = 0; qq < 4; ++qq) {
                const int u = tid + qq * 512;
                const int rr = u >> 4, seg = u & 15;
                cpasync16(sbase + ABUF3(ibuf) + ((u32)rr * AST + (u32)seg * 8u) * 2u,
                          nsrc + (size_t)(b0 + rr) * F_DIM + seg * 8);
            }
            cp_commit();
            ibuf = (ibuf == 2) ? 0 : ibuf + 1;
        }
    }

    // ---- Teardown: group barrier, reset chunk counters (replay safety) ----
    gsync_grp(&s_sense, btile);
    if (ftile == 0 && tid < NCH) {
        asm volatile("st.relaxed.gpu.global.u32 [%0], %1;"
                     :: "l"(ckbase + tid * CKS), "r"(0u) : "memory");
    }

    // ---- Projection: out[b][c] = sum_f h[b][f] * w_ph[f][c] + b_p[c] ----
    {
        const int cc = tid & 127;
        const int brow = bid * 4 + (tid >> 7);
        const __half* __restrict__ hh = g_h[0] + (size_t)brow * F_DIM;
        float a0 = 0.0f;
        #pragma unroll 4
        for (int f = 0; f < F_DIM; ++f) {
            a0 += __half2float(hh[f]) * w_ph[f * C_DIM + cc];
        }
        out[brow * C_DIM + cc] = a0 + b_p[cc];
    }
}

extern "C" void kernel_launch(void* const* d_in, const int* in_sizes, int n_in,
                              void* d_out, int out_size)
{
    (void)in_sizes; (void)n_in; (void)out_size;
    const float* x    = (const float*)d_in[0];
    const float* w_gx = (const float*)d_in[1];
    const float* w_gh = (const float*)d_in[2];
    const float* w_ix = (const float*)d_in[3];
    const float* w_ih = (const float*)d_in[4];
    const float* w_fx = (const float*)d_in[5];
    const float* w_fh = (const float*)d_in[6];
    const float* w_ox = (const float*)d_in[7];
    const float* w_oh = (const float*)d_in[8];
    const float* w_ph = (const float*)d_in[9];
    const float* b_g  = (const float*)d_in[10];
    const float* b_i  = (const float*)d_in[11];
    const float* b_f  = (const float*)d_in[12];
    const float* b_o  = (const float*)d_in[13];
    const float* b_p  = (const float*)d_in[14];
    float* out = (float*)d_out;

    cudaFuncSetAttribute(lstm_hmma_kernel,
                         cudaFuncAttributeMaxDynamicSharedMemorySize, SMEM_TOTAL);

    lstm_hmma_kernel<<<GRID_BLOCKS, THREADS, SMEM_TOTAL>>>(
        x, w_gx, w_gh, w_ix, w_ih, w_fx, w_fh, w_ox, w_oh, w_ph,
        b_g, b_i, b_f, b_o, b_p, out);
}